// round 12
// baseline (speedup 1.0000x reference)
#include <cuda_runtime.h>
#include <math.h>

#define BB    16
#define NN    8400
#define NCLS  80
#define MM    32
#define RMv   16
#define KMAX  10
#define EPSF  1e-7f
#define BN    (BB * NN)
#define TOPB  1024
#define BCEB  2100             // 2100 * 2560 = 2 * NV4B exactly
#define BCEHALF 1050
#define F4PB  2560             // float4 per BCE block
#define NV4B  2688000          // BN*NCLS/4 per branch
#define SLOTS 512              // candidate pool per (br,b,m): <=486 rect + 10 baseline

typedef unsigned long long ull;

// ---------------- persistent accumulators (reset by last block each launch) -------
__device__ double   g_bce[2] = {0.0, 0.0};
__device__ double   g_acc[8] = {0,0,0,0,0,0,0,0};  // [br*4 + {bce_t, lbox, ldfl, npos}]
__device__ unsigned g_ticket = 0;

// ---------------- helpers ---------------------------------------------------------
__device__ __forceinline__ float warpSum(float v) {
#pragma unroll
    for (int o = 16; o > 0; o >>= 1) v += __shfl_down_sync(0xffffffffu, v, o);
    return v;
}
__device__ __forceinline__ ull warpMaxU(ull v) {
#pragma unroll
    for (int o = 16; o > 0; o >>= 1) {
        ull other = __shfl_xor_sync(0xffffffffu, v, o);
        if (other > v) v = other;
    }
    return v;
}

__device__ __constant__ int LS[3]   = {8, 16, 32};
__device__ __constant__ int LG[3]   = {80, 40, 20};
__device__ __constant__ int LOFF[3] = {0, 6400, 8000};

__device__ __forceinline__ void anchor_of(int n, float& ax, float& ay, float& s) {
    int l = (n < 6400) ? 0 : ((n < 8000) ? 1 : 2);
    int g = LG[l], loc = n - LOFF[l];
    int iy = loc / g, ix = loc % g;
    s = (float)LS[l];
    ax = (ix + 0.5f) * s;
    ay = (iy + 0.5f) * s;
}

// index range [i0,i1] with (i+0.5)*s inside [lo,hi]; exact wrt float predicate
__device__ __forceinline__ int2 axis_range(float lo, float hi, float s, int g) {
    int i0 = (int)floorf(lo / s - 0.5f);
    if (i0 < 0) i0 = 0;
    while (i0 < g && (i0 + 0.5f) * s < lo) i0++;
    while (i0 > 0 && ((i0 - 1) + 0.5f) * s >= lo) i0--;
    int i1 = (int)ceilf(hi / s - 0.5f);
    if (i1 > g - 1) i1 = g - 1;
    while (i1 >= 0 && (i1 + 0.5f) * s > hi) i1--;
    while (i1 < g - 1 && ((i1 + 1) + 0.5f) * s <= hi) i1++;
    return make_int2(i0, i1);
}

// decode one anchor's bbox (noinline -> bit-identical at all call sites)
__device__ __noinline__ float4 decode_box(const float* __restrict__ regs, size_t idx,
                                          float ax, float ay, float s) {
    const float4* r4 = (const float4*)(regs + idx * 64);
    float d[4];
#pragma unroll
    for (int g = 0; g < 4; g++) {
        float4 a0 = r4[g * 4 + 0], a1 = r4[g * 4 + 1];
        float4 a2 = r4[g * 4 + 2], a3 = r4[g * 4 + 3];
        float v[16] = { a0.x,a0.y,a0.z,a0.w, a1.x,a1.y,a1.z,a1.w,
                        a2.x,a2.y,a2.z,a2.w, a3.x,a3.y,a3.z,a3.w };
        float mx = v[0];
#pragma unroll
        for (int j = 1; j < 16; j++) mx = fmaxf(mx, v[j]);
        float se = 0.f, sw = 0.f;
#pragma unroll
        for (int j = 0; j < 16; j++) {
            float e = __expf(v[j] - mx);
            se += e; sw += e * (float)j;
        }
        d[g] = sw / se;
    }
    return make_float4(ax - d[0] * s, ay - d[1] * s, ax + d[2] * s, ay + d[3] * s);
}

// align metric (noinline -> bit-identical scan vs argmax)
__device__ __noinline__ float align_fn(float x, float4 p, float ax, float ay, float4 g) {
    float pa = (p.z - p.x) * (p.w - p.y);
    float iw = fmaxf(fminf(p.z, g.z) - fmaxf(p.x, g.x), 0.f);
    float ih = fmaxf(fminf(p.w, g.w) - fmaxf(p.y, g.y), 0.f);
    float inter = iw * ih;
    float ga  = (g.z - g.x) * (g.w - g.y);
    float uni = pa + ga - inter + EPSF;
    float iou = inter / uni;
    float i2 = iou * iou;
    float i6 = i2 * i2 * i2;
    float ing = (ax >= g.x && ax <= g.z && ay >= g.y && ay <= g.w) ? 1.f : 0.f;
    float pdg = 1.f / (1.f + __expf(-x));
    return pdg * i6 * ing;
}

// ---------------- K1: lean BCE streaming kernel (proven ~7 TB/s) -------------------
__global__ __launch_bounds__(256, 6) void bce_kernel(
        const float* __restrict__ cls0, const float* __restrict__ cls1) {
    int bid = blockIdx.x, tid = threadIdx.x;
    int lane = tid & 31, wid = tid >> 5;
    int brB = (bid >= BCEHALF);
    const float4* c = (const float4*)(brB ? cls1 : cls0);
    size_t base = (size_t)(bid - (brB ? BCEHALF : 0)) * F4PB + tid;

    float acc0 = 0.f, acc1 = 0.f;
#pragma unroll
    for (int half = 0; half < 2; half++) {
        float4 v[5];
#pragma unroll
        for (int j = 0; j < 5; j++)
            v[j] = c[base + (size_t)(half * 5 + j) * 256];
        float prod0 = 1.f, prod1 = 1.f;
#pragma unroll
        for (int j = 0; j < 5; j++) {
            float4 vv = v[j];
            acc0  += fmaxf(vv.x, 0.f) + fmaxf(vv.z, 0.f);
            acc1  += fmaxf(vv.y, 0.f) + fmaxf(vv.w, 0.f);
            prod0 *= (1.f + __expf(-fabsf(vv.x))) * (1.f + __expf(-fabsf(vv.z)));
            prod1 *= (1.f + __expf(-fabsf(vv.y))) * (1.f + __expf(-fabsf(vv.w)));
        }
        acc0 += __logf(prod0);
        acc1 += __logf(prod1);
    }
    __shared__ float shr[8];
    float v0 = warpSum(acc0 + acc1);
    if (lane == 0) shr[wid] = v0;
    __syncthreads();
    if (tid < 8) {
        float w0 = shr[tid];
#pragma unroll
        for (int o = 4; o > 0; o >>= 1) w0 += __shfl_down_sync(0xffu, w0, o);
        if (tid == 0) atomicAdd(&g_bce[brB], (double)w0);
    }
}

// ---------------- K2: lean assigner + O(1) ticketed final ---------------------------
__global__ __launch_bounds__(256) void assign_kernel(
        const float* __restrict__ cls0, const float* __restrict__ cls1,
        const float* __restrict__ reg0, const float* __restrict__ reg1,
        const int* __restrict__ gl, const float* __restrict__ gb,
        const float* __restrict__ mg, float* __restrict__ out) {
    int bid = blockIdx.x, tid = threadIdx.x;    // bid 0..1023
    int lane = tid & 31, wid = tid >> 5;

    __shared__ ull    skey[SLOTS];
    __shared__ float4 sgt[MM];
    __shared__ int    slab[MM];
    __shared__ int    sel[KMAX];

    int br = bid >> 9, bm = bid & 511;
    int b = bm >> 5, m = bm & 31;
    int K = br ? 1 : KMAX;
    const float* cls  = br ? cls1 : cls0;
    const float* regs = br ? reg1 : reg0;

    if (tid < MM) {
        sgt[tid]  = ((const float4*)gb)[b * MM + tid];
        slab[tid] = gl[b * MM + tid];
    }
    skey[tid] = 0ull;
    skey[tid + 256] = 0ull;
    __syncthreads();
    float4 gt = sgt[m];
    int    lab = slab[m];

    // rectangle ranges per level (exact in-box index sets)
    int x0[3], y0[3], cw[3], cnt[3], tot = 0;
#pragma unroll
    for (int l = 0; l < 3; l++) {
        float sL = (float)LS[l];
        int2 xr = axis_range(gt.x, gt.z, sL, LG[l]);
        int2 yr = axis_range(gt.y, gt.w, sL, LG[l]);
        int w = xr.y - xr.x + 1; if (w < 0) w = 0;
        int h = yr.y - yr.x + 1; if (h < 0) h = 0;
        x0[l] = xr.x; y0[l] = yr.x; cw[l] = w;
        cnt[l] = w * h; tot += cnt[l];
    }
    if (tot > SLOTS - KMAX) tot = SLOTS - KMAX;   // safety (never hit: max 486)

    // scan rectangle candidates -> keys straight into smem pool
    for (int t = tid; t < tot; t += 256) {
        int l = 0, u = t;
        while (u >= cnt[l]) { u -= cnt[l]; l++; }
        int iy = y0[l] + u / cw[l];
        int ix = x0[l] + u % cw[l];
        int n  = LOFF[l] + iy * LG[l] + ix;
        float sL = (float)LS[l];
        float ax = (ix + 0.5f) * sL, ay = (iy + 0.5f) * sL;
        size_t idx = (size_t)b * NN + n;
        float4 p = decode_box(regs, idx, ax, ay, sL);
        float  x = cls[idx * NCLS + lab];
        float  a = align_fn(x, p, ax, ay, gt);
        skey[t] = ((ull)__float_as_uint(a) << 32) |
                  (ull)(0xFFFFFFFFu - (unsigned)n);
    }
    // zero-key baseline: 10 smallest-index anchors NOT in the box (align == 0 exactly)
    if (tid == 0) {
        int got = 0;
        for (int n = 0; n < NN && got < KMAX; n++) {
            float ax, ay, sL;
            anchor_of(n, ax, ay, sL);
            bool in = (ax >= gt.x && ax <= gt.z && ay >= gt.y && ay <= gt.w);
            if (!in) {
                skey[tot + got] = (ull)(0xFFFFFFFFu - (unsigned)n);
                got++;
            }
        }
    }
    __syncthreads();

    // ---- warp 0: K rounds of warp-max over the 512-slot pool (keys unique) -------
    float bce = 0.f, lbox = 0.f, ldfl = 0.f, np = 0.f;
    if (wid == 0) {
        for (int k = 0; k < K; k++) {
            ull best = 0; int bj = 0;
#pragma unroll
            for (int j = 0; j < SLOTS / 32; j++) {
                ull v = skey[lane + j * 32];
                if (v > best) { best = v; bj = j; }
            }
            ull win = warpMaxU(best);
            if (best == win && win != 0ull) skey[lane + bj * 32] = 0ull;  // unique
            if (lane == 0) sel[k] = (int)(0xFFFFFFFFu - (unsigned)(win & 0xFFFFFFFFull));
        }
        __syncwarp();

        // ---- winner path: inline scatter (argmax over m) + loss -------------------
        if (lane < K && mg[bm] > 0.f) {
            int n = sel[lane];
            float ax, ay, sL;
            anchor_of(n, ax, ay, sL);
            size_t idx = (size_t)b * NN + n;
            float4 p = decode_box(regs, idx, ax, ay, sL);
            // prefetch all 32 class logits (3 cache lines)
            float xv[MM];
#pragma unroll
            for (int mp = 0; mp < MM; mp++)
                xv[mp] = cls[idx * NCLS + slab[mp]];
            float best = -1.f; int bmx = 0;
#pragma unroll 4
            for (int mp = 0; mp < MM; mp++) {
                float4 g = sgt[mp];
                bool in = (ax >= g.x && ax <= g.z && ay >= g.y && ay <= g.w);
                float a = in ? align_fn(xv[mp], p, ax, ay, g) : 0.f;
                if (a > best) { best = a; bmx = mp; }   // first-occurrence argmax
            }
            if (bmx == m) {
                np = 1.f;
                float t1x = gt.x, t1y = gt.y, t2x = gt.z, t2y = gt.w;
                float p1x = p.x, p1y = p.y, p2x = p.z, p2y = p.w;
                float iw = fmaxf(fminf(p2x, t2x) - fmaxf(p1x, t1x), 0.f);
                float ih = fmaxf(fminf(p2y, t2y) - fmaxf(p1y, t1y), 0.f);
                float inter = iw * ih;
                float w1 = p2x - p1x, h1 = p2y - p1y;
                float w2 = t2x - t1x, h2 = t2y - t1y;
                float uni = w1 * h1 + w2 * h2 - inter + EPSF;
                float iou = inter / uni;
                bce = -xv[m] * iou;                 // BCE target correction term
                // CIoU (replicates reference bug: ch = max(p2y,t2y) - p1y)
                float cwd = fmaxf(p2x, t2x) - fminf(p1x, t1x);
                float chh = fmaxf(p2y, t2y) - p1y;
                float c2 = cwd * cwd + chh * chh + EPSF;
                float dx = p1x + p2x - t1x - t2x;
                float dy = p1y + p2y - t1y - t2y;
                float rho2 = (dx * dx + dy * dy) * 0.25f;
                const float pi2 = 9.869604401089358f;
                float dv = atanf(w2 / (h2 + EPSF)) - atanf(w1 / (h1 + EPSF));
                float vv = (4.0f / pi2) * dv * dv;
                float alpha = vv / (vv - iou + (1.0f + EPSF));
                lbox = 1.0f - (iou - (rho2 / c2 + vv * alpha));
                // DFL
                float tt[4] = { (ax - t1x) / sL, (ay - t1y) / sL,
                                (t2x - ax) / sL, (t2y - ay) / sL };
                const float* r = regs + idx * 64;
#pragma unroll
                for (int g2 = 0; g2 < 4; g2++) {
                    float v0 = fminf(fmaxf(tt[g2], 0.f), 14.99f);
                    int   tl = (int)v0;
                    float wwl = (float)(tl + 1) - v0;
                    float wwr = 1.0f - wwl;
                    float mx = -1e30f;
#pragma unroll
                    for (int j = 0; j < RMv; j++) mx = fmaxf(mx, r[g2 * RMv + j]);
                    float se = 0.f;
#pragma unroll
                    for (int j = 0; j < RMv; j++) se += __expf(r[g2 * RMv + j] - mx);
                    float lse = __logf(se) + mx;
                    ldfl += -(r[g2 * RMv + tl]     - lse) * wwl
                            -(r[g2 * RMv + tl + 1] - lse) * wwr;
                }
            }
        }
        // warp 0 reduce + double atomics (4 per block)
        float vals[4] = { bce, lbox, ldfl, np };
#pragma unroll
        for (int q = 0; q < 4; q++) {
            float v = warpSum(vals[q]);
            if (lane == 0 && v != 0.f) atomicAdd(&g_acc[br * 4 + q], (double)v);
        }
    }

    // ---- ticketed O(1) final (thread 0 only; its atomics precede in program order)
    if (tid == 0) {
        __threadfence();
        if (atomicAdd(&g_ticket, 1u) == TOPB - 1) {
            __threadfence();
            double t[2], c[2], bx[2], df[2];
            for (int br2 = 0; br2 < 2; br2++) {
                double bceT = g_bce[br2] + g_acc[br2 * 4 + 0];
                double lboxT = g_acc[br2 * 4 + 1];
                double ldflT = g_acc[br2 * 4 + 2];
                double nfg   = fmax(g_acc[br2 * 4 + 3], 1.0);
                c[br2]  = bceT / nfg;
                bx[br2] = lboxT / nfg;
                df[br2] = ldflT / (nfg * 4.0);
                t[br2]  = c[br2] + bx[br2] * 7.5 + df[br2] * 1.5;
            }
            out[0] = (float)(t[0] + t[1]);
            out[1] = (float)(c[0] + c[1]);
            out[2] = (float)(bx[0] + bx[1]);
            out[3] = (float)(df[0] + df[1]);
            out[4] = (float)t[0];
            out[5] = (float)t[1];
            // reset persistent state for the next graph replay
            g_bce[0] = 0.0; g_bce[1] = 0.0;
#pragma unroll
            for (int q = 0; q < 8; q++) g_acc[q] = 0.0;
            __threadfence();
            g_ticket = 0;
        }
    }
}

// ---------------- launch -------------------------------------------------------------
extern "C" void kernel_launch(void* const* d_in, const int* in_sizes, int n_in,
                              void* d_out, int out_size) {
    const float* cls0 = (const float*)d_in[0];
    const float* reg0 = (const float*)d_in[1];
    const float* cls1 = (const float*)d_in[2];
    const float* reg1 = (const float*)d_in[3];
    const int*   gl   = (const int*)d_in[6];
    const float* gb   = (const float*)d_in[7];
    const float* mg   = (const float*)d_in[8];
    float* out = (float*)d_out;

    bce_kernel<<<BCEB, 256>>>(cls0, cls1);
    assign_kernel<<<TOPB, 256>>>(cls0, cls1, reg0, reg1, gl, gb, mg, out);
}

// round 13
// speedup vs baseline: 1.0404x; 1.0404x over previous
#include <cuda_runtime.h>
#include <math.h>

#define BB    16
#define NN    8400
#define NCLS  80
#define MM    32
#define RMv   16
#define KMAX  10
#define EPSF  1e-7f
#define BN    (BB * NN)
#define TOPB  1024
#define BCEB  2100             // 2100 * 2560 = 2 * NV4B exactly
#define BCEHALF 1050
#define F4PB  2560             // float4 per BCE block
#define NV4B  2688000          // BN*NCLS/4 per branch
#define SLOTS 512              // candidate pool per (br,b,m): <=486 rect + 10 baseline
#define ATH   320              // assigner threads (10 warps: one per winner)

typedef unsigned long long ull;

// ---------------- persistent accumulators (reset by last block each launch) -------
__device__ double   g_bce[2] = {0.0, 0.0};
__device__ double   g_acc[8] = {0,0,0,0,0,0,0,0};  // [br*4 + {bce_t, lbox, ldfl, npos}]
__device__ unsigned g_ticket = 0;

// ---------------- helpers ---------------------------------------------------------
__device__ __forceinline__ float warpSum(float v) {
#pragma unroll
    for (int o = 16; o > 0; o >>= 1) v += __shfl_down_sync(0xffffffffu, v, o);
    return v;
}
__device__ __forceinline__ ull warpMaxU(ull v) {
#pragma unroll
    for (int o = 16; o > 0; o >>= 1) {
        ull other = __shfl_xor_sync(0xffffffffu, v, o);
        if (other > v) v = other;
    }
    return v;
}

__device__ __constant__ int LS[3]   = {8, 16, 32};
__device__ __constant__ int LG[3]   = {80, 40, 20};
__device__ __constant__ int LOFF[3] = {0, 6400, 8000};

__device__ __forceinline__ void anchor_of(int n, float& ax, float& ay, float& s) {
    int l = (n < 6400) ? 0 : ((n < 8000) ? 1 : 2);
    int g = LG[l], loc = n - LOFF[l];
    int iy = loc / g, ix = loc % g;
    s = (float)LS[l];
    ax = (ix + 0.5f) * s;
    ay = (iy + 0.5f) * s;
}

// index range [i0,i1] with (i+0.5)*s inside [lo,hi]; exact wrt float predicate
__device__ __forceinline__ int2 axis_range(float lo, float hi, float s, int g) {
    int i0 = (int)floorf(lo / s - 0.5f);
    if (i0 < 0) i0 = 0;
    while (i0 < g && (i0 + 0.5f) * s < lo) i0++;
    while (i0 > 0 && ((i0 - 1) + 0.5f) * s >= lo) i0--;
    int i1 = (int)ceilf(hi / s - 0.5f);
    if (i1 > g - 1) i1 = g - 1;
    while (i1 >= 0 && (i1 + 0.5f) * s > hi) i1--;
    while (i1 < g - 1 && ((i1 + 1) + 0.5f) * s <= hi) i1++;
    return make_int2(i0, i1);
}

// decode one anchor's bbox (noinline -> bit-identical at all call sites)
__device__ __noinline__ float4 decode_box(const float* __restrict__ regs, size_t idx,
                                          float ax, float ay, float s) {
    const float4* r4 = (const float4*)(regs + idx * 64);
    float d[4];
#pragma unroll
    for (int g = 0; g < 4; g++) {
        float4 a0 = r4[g * 4 + 0], a1 = r4[g * 4 + 1];
        float4 a2 = r4[g * 4 + 2], a3 = r4[g * 4 + 3];
        float v[16] = { a0.x,a0.y,a0.z,a0.w, a1.x,a1.y,a1.z,a1.w,
                        a2.x,a2.y,a2.z,a2.w, a3.x,a3.y,a3.z,a3.w };
        float mx = v[0];
#pragma unroll
        for (int j = 1; j < 16; j++) mx = fmaxf(mx, v[j]);
        float se = 0.f, sw = 0.f;
#pragma unroll
        for (int j = 0; j < 16; j++) {
            float e = __expf(v[j] - mx);
            se += e; sw += e * (float)j;
        }
        d[g] = sw / se;
    }
    return make_float4(ax - d[0] * s, ay - d[1] * s, ax + d[2] * s, ay + d[3] * s);
}

// align metric (noinline -> bit-identical scan vs argmax)
__device__ __noinline__ float align_fn(float x, float4 p, float ax, float ay, float4 g) {
    float pa = (p.z - p.x) * (p.w - p.y);
    float iw = fmaxf(fminf(p.z, g.z) - fmaxf(p.x, g.x), 0.f);
    float ih = fmaxf(fminf(p.w, g.w) - fmaxf(p.y, g.y), 0.f);
    float inter = iw * ih;
    float ga  = (g.z - g.x) * (g.w - g.y);
    float uni = pa + ga - inter + EPSF;
    float iou = inter / uni;
    float i2 = iou * iou;
    float i6 = i2 * i2 * i2;
    float ing = (ax >= g.x && ax <= g.z && ay >= g.y && ay <= g.w) ? 1.f : 0.f;
    float pdg = 1.f / (1.f + __expf(-x));
    return pdg * i6 * ing;
}

// ---------------- K1: lean BCE streaming kernel (proven ~7 TB/s) -------------------
__global__ __launch_bounds__(256, 6) void bce_kernel(
        const float* __restrict__ cls0, const float* __restrict__ cls1) {
    int bid = blockIdx.x, tid = threadIdx.x;
    int lane = tid & 31, wid = tid >> 5;
    int brB = (bid >= BCEHALF);
    const float4* c = (const float4*)(brB ? cls1 : cls0);
    size_t base = (size_t)(bid - (brB ? BCEHALF : 0)) * F4PB + tid;

    float acc0 = 0.f, acc1 = 0.f;
#pragma unroll
    for (int half = 0; half < 2; half++) {
        float4 v[5];
#pragma unroll
        for (int j = 0; j < 5; j++)
            v[j] = c[base + (size_t)(half * 5 + j) * 256];
        float prod0 = 1.f, prod1 = 1.f;
#pragma unroll
        for (int j = 0; j < 5; j++) {
            float4 vv = v[j];
            acc0  += fmaxf(vv.x, 0.f) + fmaxf(vv.z, 0.f);
            acc1  += fmaxf(vv.y, 0.f) + fmaxf(vv.w, 0.f);
            prod0 *= (1.f + __expf(-fabsf(vv.x))) * (1.f + __expf(-fabsf(vv.z)));
            prod1 *= (1.f + __expf(-fabsf(vv.y))) * (1.f + __expf(-fabsf(vv.w)));
        }
        acc0 += __logf(prod0);
        acc1 += __logf(prod1);
    }
    __shared__ float shr[8];
    float v0 = warpSum(acc0 + acc1);
    if (lane == 0) shr[wid] = v0;
    __syncthreads();
    if (tid < 8) {
        float w0 = shr[tid];
#pragma unroll
        for (int o = 4; o > 0; o >>= 1) w0 += __shfl_down_sync(0xffu, w0, o);
        if (tid == 0) atomicAdd(&g_bce[brB], (double)w0);
    }
}

// ---------------- K2: assigner with warp-per-winner loss path ----------------------
__global__ __launch_bounds__(ATH) void assign_kernel(
        const float* __restrict__ cls0, const float* __restrict__ cls1,
        const float* __restrict__ reg0, const float* __restrict__ reg1,
        const int* __restrict__ gl, const float* __restrict__ gb,
        const float* __restrict__ mg, float* __restrict__ out) {
    int bid = blockIdx.x, tid = threadIdx.x;    // bid 0..1023
    int lane = tid & 31, wid = tid >> 5;        // 10 warps

    __shared__ ull    skey[SLOTS];
    __shared__ float4 sgt[MM];
    __shared__ int    slab[MM];
    __shared__ int    sel[KMAX];
    __shared__ float  swacc[KMAX][4];

    int br = bid >> 9, bm = bid & 511;
    int b = bm >> 5, m = bm & 31;
    int K = br ? 1 : KMAX;
    const float* cls  = br ? cls1 : cls0;
    const float* regs = br ? reg1 : reg0;

    if (tid < MM) {
        sgt[tid]  = ((const float4*)gb)[b * MM + tid];
        slab[tid] = gl[b * MM + tid];
    }
    for (int i = tid; i < SLOTS; i += ATH) skey[i] = 0ull;
    __syncthreads();
    float4 gt = sgt[m];
    int    lab = slab[m];

    // rectangle ranges per level (exact in-box index sets)
    int x0[3], y0[3], cw[3], cnt[3], tot = 0;
#pragma unroll
    for (int l = 0; l < 3; l++) {
        float sL = (float)LS[l];
        int2 xr = axis_range(gt.x, gt.z, sL, LG[l]);
        int2 yr = axis_range(gt.y, gt.w, sL, LG[l]);
        int w = xr.y - xr.x + 1; if (w < 0) w = 0;
        int h = yr.y - yr.x + 1; if (h < 0) h = 0;
        x0[l] = xr.x; y0[l] = yr.x; cw[l] = w;
        cnt[l] = w * h; tot += cnt[l];
    }
    if (tot > SLOTS - KMAX) tot = SLOTS - KMAX;   // safety (never hit: max 486)

    // scan rectangle candidates -> keys straight into smem pool
    for (int t = tid; t < tot; t += ATH) {
        int l = 0, u = t;
        while (u >= cnt[l]) { u -= cnt[l]; l++; }
        int iy = y0[l] + u / cw[l];
        int ix = x0[l] + u % cw[l];
        int n  = LOFF[l] + iy * LG[l] + ix;
        float sL = (float)LS[l];
        float ax = (ix + 0.5f) * sL, ay = (iy + 0.5f) * sL;
        size_t idx = (size_t)b * NN + n;
        float4 p = decode_box(regs, idx, ax, ay, sL);
        float  x = cls[idx * NCLS + lab];
        float  a = align_fn(x, p, ax, ay, gt);
        skey[t] = ((ull)__float_as_uint(a) << 32) |
                  (ull)(0xFFFFFFFFu - (unsigned)n);
    }
    // zero-key baseline: 10 smallest-index anchors NOT in the box (align == 0 exactly)
    if (tid == 0) {
        int got = 0;
        for (int n = 0; n < NN && got < KMAX; n++) {
            float ax, ay, sL;
            anchor_of(n, ax, ay, sL);
            bool in = (ax >= gt.x && ax <= gt.z && ay >= gt.y && ay <= gt.w);
            if (!in) {
                skey[tot + got] = (ull)(0xFFFFFFFFu - (unsigned)n);
                got++;
            }
        }
    }
    __syncthreads();

    // ---- warp 0: K rounds of warp-max over the 512-slot pool (keys unique) -------
    if (wid == 0) {
        for (int k = 0; k < K; k++) {
            ull best = 0; int bj = 0;
#pragma unroll
            for (int j = 0; j < SLOTS / 32; j++) {
                ull v = skey[lane + j * 32];
                if (v > best) { best = v; bj = j; }
            }
            ull win = warpMaxU(best);
            if (best == win && win != 0ull) skey[lane + bj * 32] = 0ull;  // unique
            if (lane == 0) sel[k] = (int)(0xFFFFFFFFu - (unsigned)(win & 0xFFFFFFFFull));
        }
    }
    __syncthreads();

    // ---- winner phase: warp w owns winner w; lane mp owns GT mp --------------------
    float wbce = 0.f, wlbox = 0.f, wldfl = 0.f, wnp = 0.f;
    if (wid < K) {
        float mgv = mg[bm];
        if (mgv > 0.f) {
            int n = sel[wid];
            float ax, ay, sL;
            anchor_of(n, ax, ay, sL);
            size_t idx = (size_t)b * NN + n;
            float4 p;
            if (lane == 0) p = decode_box(regs, idx, ax, ay, sL);
            p.x = __shfl_sync(0xffffffffu, p.x, 0);
            p.y = __shfl_sync(0xffffffffu, p.y, 0);
            p.z = __shfl_sync(0xffffffffu, p.z, 0);
            p.w = __shfl_sync(0xffffffffu, p.w, 0);
            // lane-parallel argmax over the 32 GTs (first occurrence)
            float4 g = sgt[lane];
            float  x = cls[idx * NCLS + slab[lane]];
            bool in = (ax >= g.x && ax <= g.z && ay >= g.y && ay <= g.w);
            float a = in ? align_fn(x, p, ax, ay, g) : 0.f;
            ull key = ((ull)__float_as_uint(a) << 32) | (unsigned)(31 - lane);
            ull win = warpMaxU(key);
            int bmx = 31 - (int)(win & 0xFFFFFFFFull);
            if (bmx == m) {
                float xm = __shfl_sync(0xffffffffu, x, m);
                float t1x = gt.x, t1y = gt.y, t2x = gt.z, t2y = gt.w;
                float p1x = p.x, p1y = p.y, p2x = p.z, p2y = p.w;
                if (lane == 0) {
                    wnp = 1.f;
                    float iw = fmaxf(fminf(p2x, t2x) - fmaxf(p1x, t1x), 0.f);
                    float ih = fmaxf(fminf(p2y, t2y) - fmaxf(p1y, t1y), 0.f);
                    float inter = iw * ih;
                    float w1 = p2x - p1x, h1 = p2y - p1y;
                    float w2 = t2x - t1x, h2 = t2y - t1y;
                    float uni = w1 * h1 + w2 * h2 - inter + EPSF;
                    float iou = inter / uni;
                    wbce = -xm * iou;                 // BCE target correction term
                    // CIoU (replicates reference bug: ch = max(p2y,t2y) - p1y)
                    float cwd = fmaxf(p2x, t2x) - fminf(p1x, t1x);
                    float chh = fmaxf(p2y, t2y) - p1y;
                    float c2 = cwd * cwd + chh * chh + EPSF;
                    float dx = p1x + p2x - t1x - t2x;
                    float dy = p1y + p2y - t1y - t2y;
                    float rho2 = (dx * dx + dy * dy) * 0.25f;
                    const float pi2 = 9.869604401089358f;
                    float dv = atanf(w2 / (h2 + EPSF)) - atanf(w1 / (h1 + EPSF));
                    float vv = (4.0f / pi2) * dv * dv;
                    float alpha = vv / (vv - iou + (1.0f + EPSF));
                    wlbox = 1.0f - (iou - (rho2 / c2 + vv * alpha));
                }
                // DFL: lanes 0..3, one group each
                if (lane < 4) {
                    int g2 = lane;
                    float tg = (g2 == 0) ? (ax - t1x) / sL :
                               (g2 == 1) ? (ay - t1y) / sL :
                               (g2 == 2) ? (t2x - ax) / sL : (t2y - ay) / sL;
                    float v0 = fminf(fmaxf(tg, 0.f), 14.99f);
                    int   tl = (int)v0;
                    float wwl = (float)(tl + 1) - v0;
                    float wwr = 1.0f - wwl;
                    const float4* r4 = (const float4*)(regs + idx * 64 + g2 * RMv);
                    float4 a0 = r4[0], a1 = r4[1], a2 = r4[2], a3 = r4[3];
                    float rv[16] = { a0.x,a0.y,a0.z,a0.w, a1.x,a1.y,a1.z,a1.w,
                                     a2.x,a2.y,a2.z,a2.w, a3.x,a3.y,a3.z,a3.w };
                    float mx = rv[0];
#pragma unroll
                    for (int j = 1; j < 16; j++) mx = fmaxf(mx, rv[j]);
                    float se = 0.f;
#pragma unroll
                    for (int j = 0; j < 16; j++) se += __expf(rv[j] - mx);
                    float lse = __logf(se) + mx;
                    wldfl = -(rv[tl] - lse) * wwl - (rv[tl + 1] - lse) * wwr;
                }
            }
        }
    }
    // per-warp reduce, slot write, block combine, 4 double atomics
    {
        float vals[4] = { wbce, wlbox, wldfl, wnp };
#pragma unroll
        for (int q = 0; q < 4; q++) {
            float v = warpSum(vals[q]);
            if (lane == 0) swacc[wid][q] = v;
        }
    }
    __syncthreads();
    if (tid < 32) {
#pragma unroll
        for (int q = 0; q < 4; q++) {
            float v = (lane < KMAX) ? swacc[lane][q] : 0.f;
            v = warpSum(v);
            if (lane == 0 && v != 0.f) atomicAdd(&g_acc[br * 4 + q], (double)v);
        }
    }
    __syncthreads();

    // ---- ticketed O(1) final ---------------------------------------------------------
    if (tid == 0) {
        __threadfence();
        if (atomicAdd(&g_ticket, 1u) == TOPB - 1) {
            __threadfence();
            double t[2], c[2], bx[2], df[2];
            for (int br2 = 0; br2 < 2; br2++) {
                double bceT  = g_bce[br2] + g_acc[br2 * 4 + 0];
                double lboxT = g_acc[br2 * 4 + 1];
                double ldflT = g_acc[br2 * 4 + 2];
                double nfg   = fmax(g_acc[br2 * 4 + 3], 1.0);
                c[br2]  = bceT / nfg;
                bx[br2] = lboxT / nfg;
                df[br2] = ldflT / (nfg * 4.0);
                t[br2]  = c[br2] + bx[br2] * 7.5 + df[br2] * 1.5;
            }
            out[0] = (float)(t[0] + t[1]);
            out[1] = (float)(c[0] + c[1]);
            out[2] = (float)(bx[0] + bx[1]);
            out[3] = (float)(df[0] + df[1]);
            out[4] = (float)t[0];
            out[5] = (float)t[1];
            // reset persistent state for the next graph replay
            g_bce[0] = 0.0; g_bce[1] = 0.0;
#pragma unroll
            for (int q = 0; q < 8; q++) g_acc[q] = 0.0;
            __threadfence();
            g_ticket = 0;
        }
    }
}

// ---------------- launch -------------------------------------------------------------
extern "C" void kernel_launch(void* const* d_in, const int* in_sizes, int n_in,
                              void* d_out, int out_size) {
    const float* cls0 = (const float*)d_in[0];
    const float* reg0 = (const float*)d_in[1];
    const float* cls1 = (const float*)d_in[2];
    const float* reg1 = (const float*)d_in[3];
    const int*   gl   = (const int*)d_in[6];
    const float* gb   = (const float*)d_in[7];
    const float* mg   = (const float*)d_in[8];
    float* out = (float*)d_out;

    bce_kernel<<<BCEB, 256>>>(cls0, cls1);
    assign_kernel<<<TOPB, ATH>>>(cls0, cls1, reg0, reg1, gl, gb, mg, out);
}

// round 14
// speedup vs baseline: 1.1099x; 1.0668x over previous
#include <cuda_runtime.h>
#include <math.h>

#define BB    16
#define NN    8400
#define NCLS  80
#define MM    32
#define RMv   16
#define KMAX  10
#define EPSF  1e-7f
#define BN    (BB * NN)
#define TOPB  1024
#define DECB  2100             // decode blocks per branch: 2100*256 = BN*4 exactly
#define BCEB  2100
#define BCEHALF 1050
#define F4PB  2560
#define NV4B  2688000          // BN*NCLS/4 per branch
#define SLOTS 512
#define ATH   320              // assigner threads (10 warps: one per winner)

typedef unsigned long long ull;

// ---------------- scratch / accumulators -------------------------------------------
__device__ float    g_bbox[2 * (size_t)BN * 4];    // decoded boxes per (br, idx)
__device__ double   g_bce[2] = {0.0, 0.0};
__device__ double   g_acc[8] = {0,0,0,0,0,0,0,0};  // [br*4 + {bce_t, lbox, ldfl, npos}]
__device__ unsigned g_ticket = 0;

// ---------------- helpers -----------------------------------------------------------
__device__ __forceinline__ float warpSum(float v) {
#pragma unroll
    for (int o = 16; o > 0; o >>= 1) v += __shfl_down_sync(0xffffffffu, v, o);
    return v;
}
__device__ __forceinline__ ull warpMaxU(ull v) {
#pragma unroll
    for (int o = 16; o > 0; o >>= 1) {
        ull other = __shfl_xor_sync(0xffffffffu, v, o);
        if (other > v) v = other;
    }
    return v;
}

__device__ __constant__ int LS[3]   = {8, 16, 32};
__device__ __constant__ int LG[3]   = {80, 40, 20};
__device__ __constant__ int LOFF[3] = {0, 6400, 8000};

__device__ __forceinline__ void anchor_of(int n, float& ax, float& ay, float& s) {
    int l = (n < 6400) ? 0 : ((n < 8000) ? 1 : 2);
    int g = LG[l], loc = n - LOFF[l];
    int iy = loc / g, ix = loc % g;
    s = (float)LS[l];
    ax = (ix + 0.5f) * s;
    ay = (iy + 0.5f) * s;
}

// index range [i0,i1] with (i+0.5)*s inside [lo,hi]; exact wrt float predicate
__device__ __forceinline__ int2 axis_range(float lo, float hi, float s, int g) {
    int i0 = (int)floorf(lo / s - 0.5f);
    if (i0 < 0) i0 = 0;
    while (i0 < g && (i0 + 0.5f) * s < lo) i0++;
    while (i0 > 0 && ((i0 - 1) + 0.5f) * s >= lo) i0--;
    int i1 = (int)ceilf(hi / s - 0.5f);
    if (i1 > g - 1) i1 = g - 1;
    while (i1 >= 0 && (i1 + 0.5f) * s > hi) i1--;
    while (i1 < g - 1 && ((i1 + 1) + 0.5f) * s <= hi) i1++;
    return make_int2(i0, i1);
}

// align metric (noinline -> bit-identical scan vs argmax)
__device__ __noinline__ float align_fn(float x, float4 p, float ax, float ay, float4 g) {
    float pa = (p.z - p.x) * (p.w - p.y);
    float iw = fmaxf(fminf(p.z, g.z) - fmaxf(p.x, g.x), 0.f);
    float ih = fmaxf(fminf(p.w, g.w) - fmaxf(p.y, g.y), 0.f);
    float inter = iw * ih;
    float ga  = (g.z - g.x) * (g.w - g.y);
    float uni = pa + ga - inter + EPSF;
    float iou = inter / uni;
    float i2 = iou * iou;
    float i6 = i2 * i2 * i2;
    float ing = (ax >= g.x && ax <= g.z && ay >= g.y && ay <= g.w) ? 1.f : 0.f;
    float pdg = 1.f / (1.f + __expf(-x));
    return pdg * i6 * ing;
}

// ---------------- K1: fused streaming (decode family + BCE family) ------------------
__global__ __launch_bounds__(256, 5) void stream_kernel(
        const float* __restrict__ cls0, const float* __restrict__ cls1,
        const float* __restrict__ reg0, const float* __restrict__ reg1) {
    int bid = blockIdx.x, tid = threadIdx.x;
    int lane = tid & 31, wid = tid >> 5;

    if (bid < 2 * DECB) {
        // ----------------- decode family: thread per (anchor, side-group) ----------
        int br = bid / DECB;
        int t  = (bid % DECB) * 256 + tid;    // 0 .. BN*4-1
        int idx = t >> 2;                      // b*NN + n
        int g   = t & 3;
        const float* regs = br ? reg1 : reg0;
        const float4* r4 = (const float4*)(regs + (size_t)idx * 64 + g * RMv);
        float4 a0 = r4[0], a1 = r4[1], a2 = r4[2], a3 = r4[3];
        float v[16] = { a0.x,a0.y,a0.z,a0.w, a1.x,a1.y,a1.z,a1.w,
                        a2.x,a2.y,a2.z,a2.w, a3.x,a3.y,a3.z,a3.w };
        float mx = v[0];
#pragma unroll
        for (int j = 1; j < 16; j++) mx = fmaxf(mx, v[j]);
        float se = 0.f, sw = 0.f;
#pragma unroll
        for (int j = 0; j < 16; j++) {
            float e = __expf(v[j] - mx);
            se += e; sw += e * (float)j;
        }
        float dd = sw / se;
        int n = idx % NN;
        float ax, ay, s;
        anchor_of(n, ax, ay, s);
        float a = (g & 1) ? ay : ax;
        g_bbox[((size_t)br * BN + idx) * 4 + g] = (g < 2) ? (a - dd * s) : (a + dd * s);
    } else {
        // ----------------- BCE family (proven ~7 TB/s) ------------------------------
        int i0  = bid - 2 * DECB;              // 0..2099
        int brB = (i0 >= BCEHALF);
        const float4* c = (const float4*)(brB ? cls1 : cls0);
        size_t base = (size_t)(i0 - (brB ? BCEHALF : 0)) * F4PB + tid;
        float acc0 = 0.f, acc1 = 0.f;
#pragma unroll
        for (int half = 0; half < 2; half++) {
            float4 v[5];
#pragma unroll
            for (int j = 0; j < 5; j++)
                v[j] = c[base + (size_t)(half * 5 + j) * 256];
            float prod0 = 1.f, prod1 = 1.f;
#pragma unroll
            for (int j = 0; j < 5; j++) {
                float4 vv = v[j];
                acc0  += fmaxf(vv.x, 0.f) + fmaxf(vv.z, 0.f);
                acc1  += fmaxf(vv.y, 0.f) + fmaxf(vv.w, 0.f);
                prod0 *= (1.f + __expf(-fabsf(vv.x))) * (1.f + __expf(-fabsf(vv.z)));
                prod1 *= (1.f + __expf(-fabsf(vv.y))) * (1.f + __expf(-fabsf(vv.w)));
            }
            acc0 += __logf(prod0);
            acc1 += __logf(prod1);
        }
        __shared__ float shr[8];
        float v0 = warpSum(acc0 + acc1);
        if (lane == 0) shr[wid] = v0;
        __syncthreads();
        if (tid < 8) {
            float w0 = shr[tid];
#pragma unroll
            for (int o = 4; o > 0; o >>= 1) w0 += __shfl_down_sync(0xffu, w0, o);
            if (tid == 0) atomicAdd(&g_bce[brB], (double)w0);
        }
    }
}

// ---------------- K2: lean assigner (reads g_bbox) + ticketed final -----------------
__global__ __launch_bounds__(ATH) void assign_kernel(
        const float* __restrict__ cls0, const float* __restrict__ cls1,
        const float* __restrict__ reg0, const float* __restrict__ reg1,
        const int* __restrict__ gl, const float* __restrict__ gb,
        const float* __restrict__ mg, float* __restrict__ out) {
    int bid = blockIdx.x, tid = threadIdx.x;    // bid 0..1023
    int lane = tid & 31, wid = tid >> 5;        // 10 warps

    __shared__ ull    skey[SLOTS];
    __shared__ float4 sgt[MM];
    __shared__ int    slab[MM];
    __shared__ int    sel[KMAX];
    __shared__ float  swacc[KMAX][4];

    int br = bid >> 9, bm = bid & 511;
    int b = bm >> 5, m = bm & 31;
    int K = br ? 1 : KMAX;
    const float* cls  = br ? cls1 : cls0;
    const float* regs = br ? reg1 : reg0;
    const float4* bbox4 = (const float4*)g_bbox + (size_t)br * BN + (size_t)b * NN;

    if (tid < MM) {
        sgt[tid]  = ((const float4*)gb)[b * MM + tid];
        slab[tid] = gl[b * MM + tid];
    }
    for (int i = tid; i < SLOTS; i += ATH) skey[i] = 0ull;
    __syncthreads();
    float4 gt = sgt[m];
    int    lab = slab[m];

    // rectangle ranges per level (exact in-box index sets)
    int x0[3], y0[3], cw[3], cnt[3], tot = 0;
#pragma unroll
    for (int l = 0; l < 3; l++) {
        float sL = (float)LS[l];
        int2 xr = axis_range(gt.x, gt.z, sL, LG[l]);
        int2 yr = axis_range(gt.y, gt.w, sL, LG[l]);
        int w = xr.y - xr.x + 1; if (w < 0) w = 0;
        int h = yr.y - yr.x + 1; if (h < 0) h = 0;
        x0[l] = xr.x; y0[l] = yr.x; cw[l] = w;
        cnt[l] = w * h; tot += cnt[l];
    }
    if (tot > SLOTS - KMAX) tot = SLOTS - KMAX;   // safety (never hit: max 486)

    // scan rectangle candidates: 16B bbox + 4B cls per candidate
    for (int t = tid; t < tot; t += ATH) {
        int l = 0, u = t;
        while (u >= cnt[l]) { u -= cnt[l]; l++; }
        int iy = y0[l] + u / cw[l];
        int ix = x0[l] + u % cw[l];
        int n  = LOFF[l] + iy * LG[l] + ix;
        float sL = (float)LS[l];
        float ax = (ix + 0.5f) * sL, ay = (iy + 0.5f) * sL;
        float4 p = bbox4[n];
        float  x = cls[((size_t)b * NN + n) * NCLS + lab];
        float  a = align_fn(x, p, ax, ay, gt);
        skey[t] = ((ull)__float_as_uint(a) << 32) |
                  (ull)(0xFFFFFFFFu - (unsigned)n);
    }
    // zero-key baseline: 10 smallest-index anchors NOT in the box (align == 0 exactly)
    if (tid == 0) {
        int got = 0;
        for (int n = 0; n < NN && got < KMAX; n++) {
            float ax, ay, sL;
            anchor_of(n, ax, ay, sL);
            bool in = (ax >= gt.x && ax <= gt.z && ay >= gt.y && ay <= gt.w);
            if (!in) {
                skey[tot + got] = (ull)(0xFFFFFFFFu - (unsigned)n);
                got++;
            }
        }
    }
    __syncthreads();

    // ---- warp 0: K rounds of warp-max over the 512-slot pool (keys unique) --------
    if (wid == 0) {
        for (int k = 0; k < K; k++) {
            ull best = 0; int bj = 0;
#pragma unroll
            for (int j = 0; j < SLOTS / 32; j++) {
                ull v = skey[lane + j * 32];
                if (v > best) { best = v; bj = j; }
            }
            ull win = warpMaxU(best);
            if (best == win && win != 0ull) skey[lane + bj * 32] = 0ull;  // unique
            if (lane == 0) sel[k] = (int)(0xFFFFFFFFu - (unsigned)(win & 0xFFFFFFFFull));
        }
    }
    __syncthreads();

    // ---- winner phase: warp w owns winner w; lane mp owns GT mp ---------------------
    float wbce = 0.f, wlbox = 0.f, wldfl = 0.f, wnp = 0.f;
    if (wid < K) {
        float mgv = mg[bm];
        if (mgv > 0.f) {
            int n = sel[wid];
            float ax, ay, sL;
            anchor_of(n, ax, ay, sL);
            size_t idx = (size_t)b * NN + n;
            float4 p = bbox4[n];
            // lane-parallel argmax over the 32 GTs (first occurrence)
            float4 g = sgt[lane];
            float  x = cls[idx * NCLS + slab[lane]];
            bool in = (ax >= g.x && ax <= g.z && ay >= g.y && ay <= g.w);
            float a = in ? align_fn(x, p, ax, ay, g) : 0.f;
            ull key = ((ull)__float_as_uint(a) << 32) | (unsigned)(31 - lane);
            ull win = warpMaxU(key);
            int bmx = 31 - (int)(win & 0xFFFFFFFFull);
            if (bmx == m) {
                float xm = __shfl_sync(0xffffffffu, x, m);
                float t1x = gt.x, t1y = gt.y, t2x = gt.z, t2y = gt.w;
                float p1x = p.x, p1y = p.y, p2x = p.z, p2y = p.w;
                if (lane == 0) {
                    wnp = 1.f;
                    float iw = fmaxf(fminf(p2x, t2x) - fmaxf(p1x, t1x), 0.f);
                    float ih = fmaxf(fminf(p2y, t2y) - fmaxf(p1y, t1y), 0.f);
                    float inter = iw * ih;
                    float w1 = p2x - p1x, h1 = p2y - p1y;
                    float w2 = t2x - t1x, h2 = t2y - t1y;
                    float uni = w1 * h1 + w2 * h2 - inter + EPSF;
                    float iou = inter / uni;
                    wbce = -xm * iou;                 // BCE target correction term
                    // CIoU (replicates reference bug: ch = max(p2y,t2y) - p1y)
                    float cwd = fmaxf(p2x, t2x) - fminf(p1x, t1x);
                    float chh = fmaxf(p2y, t2y) - p1y;
                    float c2 = cwd * cwd + chh * chh + EPSF;
                    float dx = p1x + p2x - t1x - t2x;
                    float dy = p1y + p2y - t1y - t2y;
                    float rho2 = (dx * dx + dy * dy) * 0.25f;
                    const float pi2 = 9.869604401089358f;
                    float dv = atanf(w2 / (h2 + EPSF)) - atanf(w1 / (h1 + EPSF));
                    float vv = (4.0f / pi2) * dv * dv;
                    float alpha = vv / (vv - iou + (1.0f + EPSF));
                    wlbox = 1.0f - (iou - (rho2 / c2 + vv * alpha));
                }
                // DFL: lanes 0..3, one group each
                if (lane < 4) {
                    int g2 = lane;
                    float tg = (g2 == 0) ? (ax - t1x) / sL :
                               (g2 == 1) ? (ay - t1y) / sL :
                               (g2 == 2) ? (t2x - ax) / sL : (t2y - ay) / sL;
                    float v0 = fminf(fmaxf(tg, 0.f), 14.99f);
                    int   tl = (int)v0;
                    float wwl = (float)(tl + 1) - v0;
                    float wwr = 1.0f - wwl;
                    const float4* r4 = (const float4*)(regs + idx * 64 + g2 * RMv);
                    float4 a0 = r4[0], a1 = r4[1], a2 = r4[2], a3 = r4[3];
                    float rv[16] = { a0.x,a0.y,a0.z,a0.w, a1.x,a1.y,a1.z,a1.w,
                                     a2.x,a2.y,a2.z,a2.w, a3.x,a3.y,a3.z,a3.w };
                    float mx = rv[0];
#pragma unroll
                    for (int j = 1; j < 16; j++) mx = fmaxf(mx, rv[j]);
                    float se = 0.f;
#pragma unroll
                    for (int j = 0; j < 16; j++) se += __expf(rv[j] - mx);
                    float lse = __logf(se) + mx;
                    wldfl = -(rv[tl] - lse) * wwl - (rv[tl + 1] - lse) * wwr;
                }
            }
        }
    }
    // per-warp reduce, slot write, block combine, 4 double atomics
    {
        float vals[4] = { wbce, wlbox, wldfl, wnp };
#pragma unroll
        for (int q = 0; q < 4; q++) {
            float v = warpSum(vals[q]);
            if (lane == 0) swacc[wid][q] = v;
        }
    }
    __syncthreads();
    if (tid < 32) {
#pragma unroll
        for (int q = 0; q < 4; q++) {
            float v = (lane < KMAX) ? swacc[lane][q] : 0.f;
            v = warpSum(v);
            if (lane == 0 && v != 0.f) atomicAdd(&g_acc[br * 4 + q], (double)v);
        }
    }
    __syncthreads();

    // ---- ticketed O(1) final ----------------------------------------------------------
    if (tid == 0) {
        __threadfence();
        if (atomicAdd(&g_ticket, 1u) == TOPB - 1) {
            __threadfence();
            double t[2], c[2], bx[2], df[2];
            for (int br2 = 0; br2 < 2; br2++) {
                double bceT  = g_bce[br2] + g_acc[br2 * 4 + 0];
                double lboxT = g_acc[br2 * 4 + 1];
                double ldflT = g_acc[br2 * 4 + 2];
                double nfg   = fmax(g_acc[br2 * 4 + 3], 1.0);
                c[br2]  = bceT / nfg;
                bx[br2] = lboxT / nfg;
                df[br2] = ldflT / (nfg * 4.0);
                t[br2]  = c[br2] + bx[br2] * 7.5 + df[br2] * 1.5;
            }
            out[0] = (float)(t[0] + t[1]);
            out[1] = (float)(c[0] + c[1]);
            out[2] = (float)(bx[0] + bx[1]);
            out[3] = (float)(df[0] + df[1]);
            out[4] = (float)t[0];
            out[5] = (float)t[1];
            // reset persistent state for the next graph replay
            g_bce[0] = 0.0; g_bce[1] = 0.0;
#pragma unroll
            for (int q = 0; q < 8; q++) g_acc[q] = 0.0;
            __threadfence();
            g_ticket = 0;
        }
    }
}

// ---------------- launch ---------------------------------------------------------------
extern "C" void kernel_launch(void* const* d_in, const int* in_sizes, int n_in,
                              void* d_out, int out_size) {
    const float* cls0 = (const float*)d_in[0];
    const float* reg0 = (const float*)d_in[1];
    const float* cls1 = (const float*)d_in[2];
    const float* reg1 = (const float*)d_in[3];
    const int*   gl   = (const int*)d_in[6];
    const float* gb   = (const float*)d_in[7];
    const float* mg   = (const float*)d_in[8];
    float* out = (float*)d_out;

    stream_kernel<<<2 * DECB + BCEB, 256>>>(cls0, cls1, reg0, reg1);
    assign_kernel<<<TOPB, ATH>>>(cls0, cls1, reg0, reg1, gl, gb, mg, out);
}

// round 15
// speedup vs baseline: 1.2111x; 1.0912x over previous
#include <cuda_runtime.h>
#include <math.h>

#define BB    16
#define NN    8400
#define NCLS  80
#define MM    32
#define RMv   16
#define KMAX  10
#define EPSF  1e-7f
#define BN    (BB * NN)
#define ABLK  512              // assigner blocks: one per (b,m), both branches inside
#define DECB  2100             // decode blocks per branch: 2100*256 = BN*4 exactly
#define BCEB  2100
#define BCEHALF 1050
#define F4PB  2560
#define NV4B  2688000          // BN*NCLS/4 per branch
#define SLOTS 512
#define ATH   320              // assigner threads (10 warps: one per winner)

typedef unsigned long long ull;

// ---------------- scratch / accumulators -------------------------------------------
__device__ float    g_bbox[2 * (size_t)BN * 4];    // decoded boxes per (br, idx)
__device__ double   g_bce[2] = {0.0, 0.0};
__device__ double   g_acc[8] = {0,0,0,0,0,0,0,0};  // [br*4 + {bce_t, lbox, ldfl, npos}]
__device__ unsigned g_ticket = 0;

// ---------------- helpers -----------------------------------------------------------
__device__ __forceinline__ float warpSum(float v) {
#pragma unroll
    for (int o = 16; o > 0; o >>= 1) v += __shfl_down_sync(0xffffffffu, v, o);
    return v;
}
__device__ __forceinline__ ull warpMaxU(ull v) {
#pragma unroll
    for (int o = 16; o > 0; o >>= 1) {
        ull other = __shfl_xor_sync(0xffffffffu, v, o);
        if (other > v) v = other;
    }
    return v;
}

__device__ __constant__ int LS[3]   = {8, 16, 32};
__device__ __constant__ int LG[3]   = {80, 40, 20};
__device__ __constant__ int LOFF[3] = {0, 6400, 8000};

__device__ __forceinline__ void anchor_of(int n, float& ax, float& ay, float& s) {
    int l = (n < 6400) ? 0 : ((n < 8000) ? 1 : 2);
    int g = LG[l], loc = n - LOFF[l];
    int iy = loc / g, ix = loc % g;
    s = (float)LS[l];
    ax = (ix + 0.5f) * s;
    ay = (iy + 0.5f) * s;
}

// index range [i0,i1] with (i+0.5)*s inside [lo,hi]; exact wrt float predicate
__device__ __forceinline__ int2 axis_range(float lo, float hi, float s, int g) {
    int i0 = (int)floorf(lo / s - 0.5f);
    if (i0 < 0) i0 = 0;
    while (i0 < g && (i0 + 0.5f) * s < lo) i0++;
    while (i0 > 0 && ((i0 - 1) + 0.5f) * s >= lo) i0--;
    int i1 = (int)ceilf(hi / s - 0.5f);
    if (i1 > g - 1) i1 = g - 1;
    while (i1 >= 0 && (i1 + 0.5f) * s > hi) i1--;
    while (i1 < g - 1 && ((i1 + 1) + 0.5f) * s <= hi) i1++;
    return make_int2(i0, i1);
}

// align metric (noinline -> bit-identical scan vs argmax)
__device__ __noinline__ float align_fn(float x, float4 p, float ax, float ay, float4 g) {
    float pa = (p.z - p.x) * (p.w - p.y);
    float iw = fmaxf(fminf(p.z, g.z) - fmaxf(p.x, g.x), 0.f);
    float ih = fmaxf(fminf(p.w, g.w) - fmaxf(p.y, g.y), 0.f);
    float inter = iw * ih;
    float ga  = (g.z - g.x) * (g.w - g.y);
    float uni = pa + ga - inter + EPSF;
    float iou = inter / uni;
    float i2 = iou * iou;
    float i6 = i2 * i2 * i2;
    float ing = (ax >= g.x && ax <= g.z && ay >= g.y && ay <= g.w) ? 1.f : 0.f;
    float pdg = 1.f / (1.f + __expf(-x));
    return pdg * i6 * ing;
}

// ---------------- K1: fused streaming (decode family + BCE family) ------------------
__global__ __launch_bounds__(256, 5) void stream_kernel(
        const float* __restrict__ cls0, const float* __restrict__ cls1,
        const float* __restrict__ reg0, const float* __restrict__ reg1) {
    int bid = blockIdx.x, tid = threadIdx.x;
    int lane = tid & 31, wid = tid >> 5;

    if (bid < 2 * DECB) {
        // ----------------- decode family: thread per (anchor, side-group) ----------
        int br = bid / DECB;
        int t  = (bid % DECB) * 256 + tid;    // 0 .. BN*4-1
        int idx = t >> 2;                      // b*NN + n
        int g   = t & 3;
        const float* regs = br ? reg1 : reg0;
        const float4* r4 = (const float4*)(regs + (size_t)idx * 64 + g * RMv);
        float4 a0 = r4[0], a1 = r4[1], a2 = r4[2], a3 = r4[3];
        float v[16] = { a0.x,a0.y,a0.z,a0.w, a1.x,a1.y,a1.z,a1.w,
                        a2.x,a2.y,a2.z,a2.w, a3.x,a3.y,a3.z,a3.w };
        float mx = v[0];
#pragma unroll
        for (int j = 1; j < 16; j++) mx = fmaxf(mx, v[j]);
        float se = 0.f, sw = 0.f;
#pragma unroll
        for (int j = 0; j < 16; j++) {
            float e = __expf(v[j] - mx);
            se += e; sw += e * (float)j;
        }
        float dd = sw / se;
        int n = idx % NN;
        float ax, ay, s;
        anchor_of(n, ax, ay, s);
        float a = (g & 1) ? ay : ax;
        g_bbox[((size_t)br * BN + idx) * 4 + g] = (g < 2) ? (a - dd * s) : (a + dd * s);
    } else {
        // ----------------- BCE family (proven ~7 TB/s) ------------------------------
        int i0  = bid - 2 * DECB;              // 0..2099
        int brB = (i0 >= BCEHALF);
        const float4* c = (const float4*)(brB ? cls1 : cls0);
        size_t base = (size_t)(i0 - (brB ? BCEHALF : 0)) * F4PB + tid;
        float acc0 = 0.f, acc1 = 0.f;
#pragma unroll
        for (int half = 0; half < 2; half++) {
            float4 v[5];
#pragma unroll
            for (int j = 0; j < 5; j++)
                v[j] = c[base + (size_t)(half * 5 + j) * 256];
            float prod0 = 1.f, prod1 = 1.f;
#pragma unroll
            for (int j = 0; j < 5; j++) {
                float4 vv = v[j];
                acc0  += fmaxf(vv.x, 0.f) + fmaxf(vv.z, 0.f);
                acc1  += fmaxf(vv.y, 0.f) + fmaxf(vv.w, 0.f);
                prod0 *= (1.f + __expf(-fabsf(vv.x))) * (1.f + __expf(-fabsf(vv.z)));
                prod1 *= (1.f + __expf(-fabsf(vv.y))) * (1.f + __expf(-fabsf(vv.w)));
            }
            acc0 += __logf(prod0);
            acc1 += __logf(prod1);
        }
        __shared__ float shr[8];
        float v0 = warpSum(acc0 + acc1);
        if (lane == 0) shr[wid] = v0;
        __syncthreads();
        if (tid < 8) {
            float w0 = shr[tid];
#pragma unroll
            for (int o = 4; o > 0; o >>= 1) w0 += __shfl_down_sync(0xffu, w0, o);
            if (tid == 0) atomicAdd(&g_bce[brB], (double)w0);
        }
    }
}

// ---------------- K2: assigner, both branches per block, lane-parallel winner -------
__global__ __launch_bounds__(ATH, 3) void assign_kernel(
        const float* __restrict__ cls0, const float* __restrict__ cls1,
        const float* __restrict__ reg0, const float* __restrict__ reg1,
        const int* __restrict__ gl, const float* __restrict__ gb,
        const float* __restrict__ mg, float* __restrict__ out) {
    int bm = blockIdx.x, tid = threadIdx.x;     // bm 0..511
    int lane = tid & 31, wid = tid >> 5;        // 10 warps
    int b = bm >> 5, m = bm & 31;

    __shared__ ull    skey[SLOTS];
    __shared__ float4 sgt[MM];
    __shared__ int    slab[MM];
    __shared__ int    sel[KMAX];
    __shared__ int    sbase[KMAX];              // zero-key baseline anchor ids
    __shared__ float  swacc[KMAX][4];

    if (tid < MM) {
        sgt[tid]  = ((const float4*)gb)[b * MM + tid];
        slab[tid] = gl[b * MM + tid];
    }
    __syncthreads();
    float4 gt = sgt[m];
    int    lab = slab[m];
    float  mgv = mg[bm];

    // rectangle ranges per level (exact in-box index sets) — same for both branches
    int2 xr0 = axis_range(gt.x, gt.z, 8.f,  80);
    int2 yr0 = axis_range(gt.y, gt.w, 8.f,  80);
    int2 xr1 = axis_range(gt.x, gt.z, 16.f, 40);
    int2 yr1 = axis_range(gt.y, gt.w, 16.f, 40);
    int2 xr2 = axis_range(gt.x, gt.z, 32.f, 20);
    int2 yr2 = axis_range(gt.y, gt.w, 32.f, 20);
    int w0c = max(xr0.y - xr0.x + 1, 0), h0c = max(yr0.y - yr0.x + 1, 0);
    int w1c = max(xr1.y - xr1.x + 1, 0), h1c = max(yr1.y - yr1.x + 1, 0);
    int w2c = max(xr2.y - xr2.x + 1, 0), h2c = max(yr2.y - yr2.x + 1, 0);
    int cnt0 = w0c * h0c, cnt1 = w1c * h1c, cnt2 = w2c * h2c;
    int tot = cnt0 + cnt1 + cnt2;
    if (tot > SLOTS - KMAX) tot = SLOTS - KMAX;   // safety (never hit: max ~486)

    // zero-key baseline indices (same for both branches)
    if (tid == 0) {
        int got = 0;
        for (int n = 0; n < NN && got < KMAX; n++) {
            float ax, ay, sL;
            anchor_of(n, ax, ay, sL);
            bool in = (ax >= gt.x && ax <= gt.z && ay >= gt.y && ay <= gt.w);
            if (!in) { sbase[got] = n; got++; }
        }
    }

    for (int br = 0; br < 2; br++) {
        int K = br ? 1 : KMAX;
        const float* cls  = br ? cls1 : cls0;
        const float* regs = br ? reg1 : reg0;
        const float4* bbox4 = (const float4*)g_bbox + (size_t)br * BN + (size_t)b * NN;

        for (int i = tid; i < SLOTS; i += ATH) skey[i] = 0ull;
        __syncthreads();

        // scan rectangle candidates: 16B bbox + 4B cls per candidate
        for (int t = tid; t < tot; t += ATH) {
            int l, u = t, gx0, gy0, gw, gL, goff;
            float sL;
            if (u < cnt0)      { l = 0; gx0 = xr0.x; gy0 = yr0.x; gw = w0c; gL = 80; goff = 0;    sL = 8.f; }
            else { u -= cnt0;
              if (u < cnt1)    { l = 1; gx0 = xr1.x; gy0 = yr1.x; gw = w1c; gL = 40; goff = 6400; sL = 16.f; }
              else { u -= cnt1;  l = 2; gx0 = xr2.x; gy0 = yr2.x; gw = w2c; gL = 20; goff = 8000; sL = 32.f; }
            }
            int iy = gy0 + u / gw;
            int ix = gx0 + u % gw;
            int n  = goff + iy * gL + ix;
            float ax = (ix + 0.5f) * sL, ay = (iy + 0.5f) * sL;
            float4 p = bbox4[n];
            float  x = cls[((size_t)b * NN + n) * NCLS + lab];
            float  a = align_fn(x, p, ax, ay, gt);
            skey[t] = ((ull)__float_as_uint(a) << 32) |
                      (ull)(0xFFFFFFFFu - (unsigned)n);
        }
        if (tid < KMAX)
            skey[tot + tid] = (ull)(0xFFFFFFFFu - (unsigned)sbase[tid]);
        __syncthreads();

        // ---- warp 0: K rounds of warp-max over the pool (keys unique) -------------
        if (wid == 0) {
            for (int k = 0; k < K; k++) {
                ull best = 0; int bj = 0;
#pragma unroll
                for (int j = 0; j < SLOTS / 32; j++) {
                    ull v = skey[lane + j * 32];
                    if (v > best) { best = v; bj = j; }
                }
                ull win = warpMaxU(best);
                if (best == win && win != 0ull) skey[lane + bj * 32] = 0ull;
                if (lane == 0) sel[k] = (int)(0xFFFFFFFFu - (unsigned)(win & 0xFFFFFFFFull));
            }
        }
        __syncthreads();

        // ---- winner phase: warp w owns winner w; lane mp owns GT mp ----------------
        float wbce = 0.f, wlbox = 0.f, wldfl = 0.f, wnp = 0.f;
        if (wid < K && mgv > 0.f) {
            int n = sel[wid];
            float ax, ay, sL;
            anchor_of(n, ax, ay, sL);
            size_t idx = (size_t)b * NN + n;
            float4 p = bbox4[n];
            // lane-parallel argmax over the 32 GTs (first occurrence)
            float4 g = sgt[lane];
            float  x = cls[idx * NCLS + slab[lane]];
            bool in = (ax >= g.x && ax <= g.z && ay >= g.y && ay <= g.w);
            float a = in ? align_fn(x, p, ax, ay, g) : 0.f;
            ull key = ((ull)__float_as_uint(a) << 32) | (unsigned)(31 - lane);
            ull win = warpMaxU(key);
            int bmx = 31 - (int)(win & 0xFFFFFFFFull);
            if (bmx == m) {
                float xm = __shfl_sync(0xffffffffu, x, m);
                float t1x = gt.x, t1y = gt.y, t2x = gt.z, t2y = gt.w;
                float p1x = p.x, p1y = p.y, p2x = p.z, p2y = p.w;
                if (lane == 0) {
                    wnp = 1.f;
                    float iw = fmaxf(fminf(p2x, t2x) - fmaxf(p1x, t1x), 0.f);
                    float ih = fmaxf(fminf(p2y, t2y) - fmaxf(p1y, t1y), 0.f);
                    float inter = iw * ih;
                    float w1 = p2x - p1x, h1 = p2y - p1y;
                    float w2 = t2x - t1x, h2 = t2y - t1y;
                    float uni = w1 * h1 + w2 * h2 - inter + EPSF;
                    float iou = inter / uni;
                    wbce = -xm * iou;               // BCE target correction term
                    // CIoU (replicates reference bug: ch = max(p2y,t2y) - p1y)
                    float cwd = fmaxf(p2x, t2x) - fminf(p1x, t1x);
                    float chh = fmaxf(p2y, t2y) - p1y;
                    float c2 = cwd * cwd + chh * chh + EPSF;
                    float dx = p1x + p2x - t1x - t2x;
                    float dy = p1y + p2y - t1y - t2y;
                    float rho2 = (dx * dx + dy * dy) * 0.25f;
                    const float pi2 = 9.869604401089358f;
                    float dv = atanf(w2 / (h2 + EPSF)) - atanf(w1 / (h1 + EPSF));
                    float vv = (4.0f / pi2) * dv * dv;
                    float alpha = vv / (vv - iou + (1.0f + EPSF));
                    wlbox = 1.0f - (iou - (rho2 / c2 + vv * alpha));
                }
                // ---- lane-parallel DFL: lane holds r[lane] (groups 0,1) and r[lane+32]
                const float* r = regs + idx * 64;
                float v0 = r[lane];          // group = lane/16 (0 or 1)
                float v1 = r[lane + 32];     // group = 2 + lane/16
                float m0 = v0, m1 = v1;
#pragma unroll
                for (int o = 8; o > 0; o >>= 1) {
                    m0 = fmaxf(m0, __shfl_xor_sync(0xffffffffu, m0, o));
                    m1 = fmaxf(m1, __shfl_xor_sync(0xffffffffu, m1, o));
                }
                float e0 = __expf(v0 - m0), e1 = __expf(v1 - m1);
#pragma unroll
                for (int o = 8; o > 0; o >>= 1) {
                    e0 += __shfl_xor_sync(0xffffffffu, e0, o);
                    e1 += __shfl_xor_sync(0xffffffffu, e1, o);
                }
                float lse0 = __logf(e0) + m0;   // group (lane<16?0:1)
                float lse1 = __logf(e1) + m1;   // group (lane<16?2:3)
                // lanes 0..3 compute one group each; all lanes run the shfls
                int gsel = lane & 3;
                float tg = (gsel == 0) ? (ax - t1x) / sL :
                           (gsel == 1) ? (ay - t1y) / sL :
                           (gsel == 2) ? (t2x - ax) / sL : (t2y - ay) / sL;
                float vc = fminf(fmaxf(tg, 0.f), 14.99f);
                int   tl = (int)vc;
                float wwl = (float)(tl + 1) - vc;
                float wwr = 1.0f - wwl;
                int half = (gsel & 1) * 16;
                float lA  = __shfl_sync(0xffffffffu, lse0, half);
                float lB  = __shfl_sync(0xffffffffu, lse1, half);
                float rA0 = __shfl_sync(0xffffffffu, v0, half + tl);
                float rB0 = __shfl_sync(0xffffffffu, v1, half + tl);
                float rA1 = __shfl_sync(0xffffffffu, v0, half + tl + 1);
                float rB1 = __shfl_sync(0xffffffffu, v1, half + tl + 1);
                float lseg = (gsel < 2) ? lA : lB;
                float rtl  = (gsel < 2) ? rA0 : rB0;
                float rtr  = (gsel < 2) ? rA1 : rB1;
                float dfl = -(rtl - lseg) * wwl - (rtr - lseg) * wwr;
                wldfl = (lane < 4) ? dfl : 0.f;
            }
        }
        // per-warp reduce, slot write, block combine, 4 double atomics
        {
            float vals[4] = { wbce, wlbox, wldfl, wnp };
#pragma unroll
            for (int q = 0; q < 4; q++) {
                float v = warpSum(vals[q]);
                if (lane == 0) swacc[wid][q] = (wid < K) ? v : 0.f;
            }
        }
        __syncthreads();
        if (tid < 32) {
#pragma unroll
            for (int q = 0; q < 4; q++) {
                float v = (lane < KMAX) ? swacc[lane][q] : 0.f;
                v = warpSum(v);
                if (lane == 0 && v != 0.f) atomicAdd(&g_acc[br * 4 + q], (double)v);
            }
        }
        __syncthreads();
    }

    // ---- ticketed O(1) final ------------------------------------------------------
    if (tid == 0) {
        __threadfence();
        if (atomicAdd(&g_ticket, 1u) == ABLK - 1) {
            __threadfence();
            double t[2], c[2], bx[2], df[2];
            for (int br2 = 0; br2 < 2; br2++) {
                double bceT  = g_bce[br2] + g_acc[br2 * 4 + 0];
                double lboxT = g_acc[br2 * 4 + 1];
                double ldflT = g_acc[br2 * 4 + 2];
                double nfg   = fmax(g_acc[br2 * 4 + 3], 1.0);
                c[br2]  = bceT / nfg;
                bx[br2] = lboxT / nfg;
                df[br2] = ldflT / (nfg * 4.0);
                t[br2]  = c[br2] + bx[br2] * 7.5 + df[br2] * 1.5;
            }
            out[0] = (float)(t[0] + t[1]);
            out[1] = (float)(c[0] + c[1]);
            out[2] = (float)(bx[0] + bx[1]);
            out[3] = (float)(df[0] + df[1]);
            out[4] = (float)t[0];
            out[5] = (float)t[1];
            // reset persistent state for the next graph replay
            g_bce[0] = 0.0; g_bce[1] = 0.0;
#pragma unroll
            for (int q = 0; q < 8; q++) g_acc[q] = 0.0;
            __threadfence();
            g_ticket = 0;
        }
    }
}

// ---------------- launch ---------------------------------------------------------------
extern "C" void kernel_launch(void* const* d_in, const int* in_sizes, int n_in,
                              void* d_out, int out_size) {
    const float* cls0 = (const float*)d_in[0];
    const float* reg0 = (const float*)d_in[1];
    const float* cls1 = (const float*)d_in[2];
    const float* reg1 = (const float*)d_in[3];
    const int*   gl   = (const int*)d_in[6];
    const float* gb   = (const float*)d_in[7];
    const float* mg   = (const float*)d_in[8];
    float* out = (float*)d_out;

    stream_kernel<<<2 * DECB + BCEB, 256>>>(cls0, cls1, reg0, reg1);
    assign_kernel<<<ABLK, ATH>>>(cls0, cls1, reg0, reg1, gl, gb, mg, out);
}

// round 16
// speedup vs baseline: 1.3306x; 1.0987x over previous
#include <cuda_runtime.h>
#include <math.h>

#define BB    16
#define NN    8400
#define NCLS  80
#define MM    32
#define RMv   16
#define KMAX  10
#define EPSF  1e-7f
#define BN    (BB * NN)
#define ABLK  512              // assigner blocks: one per (b,m), both branches parallel
#define DECB  2100             // decode blocks per branch: 2100*256 = BN*4 exactly
#define BCEB  2100
#define BCEHALF 1050
#define F4PB  2560
#define NV4B  2688000          // BN*NCLS/4 per branch
#define SLOTS 512
#define ATH   320              // assigner threads (10 warps)

typedef unsigned long long ull;

// ---------------- scratch / accumulators -------------------------------------------
__device__ float    g_bbox[2 * (size_t)BN * 4];    // decoded boxes per (br, idx)
__device__ double   g_bce[2] = {0.0, 0.0};
__device__ double   g_acc[8] = {0,0,0,0,0,0,0,0};  // [br*4 + {bce_t, lbox, ldfl, npos}]
__device__ unsigned g_ticket = 0;

// ---------------- helpers -----------------------------------------------------------
__device__ __forceinline__ float warpSum(float v) {
#pragma unroll
    for (int o = 16; o > 0; o >>= 1) v += __shfl_down_sync(0xffffffffu, v, o);
    return v;
}
__device__ __forceinline__ ull warpMaxU(ull v) {
#pragma unroll
    for (int o = 16; o > 0; o >>= 1) {
        ull other = __shfl_xor_sync(0xffffffffu, v, o);
        if (other > v) v = other;
    }
    return v;
}

__device__ __constant__ int LS[3]   = {8, 16, 32};
__device__ __constant__ int LG[3]   = {80, 40, 20};
__device__ __constant__ int LOFF[3] = {0, 6400, 8000};

__device__ __forceinline__ void anchor_of(int n, float& ax, float& ay, float& s) {
    int l = (n < 6400) ? 0 : ((n < 8000) ? 1 : 2);
    int g = LG[l], loc = n - LOFF[l];
    int iy = loc / g, ix = loc % g;
    s = (float)LS[l];
    ax = (ix + 0.5f) * s;
    ay = (iy + 0.5f) * s;
}

// index range [i0,i1] with (i+0.5)*s inside [lo,hi]; exact wrt float predicate
__device__ __forceinline__ int2 axis_range(float lo, float hi, float s, int g) {
    int i0 = (int)floorf(lo / s - 0.5f);
    if (i0 < 0) i0 = 0;
    while (i0 < g && (i0 + 0.5f) * s < lo) i0++;
    while (i0 > 0 && ((i0 - 1) + 0.5f) * s >= lo) i0--;
    int i1 = (int)ceilf(hi / s - 0.5f);
    if (i1 > g - 1) i1 = g - 1;
    while (i1 >= 0 && (i1 + 0.5f) * s > hi) i1--;
    while (i1 < g - 1 && ((i1 + 1) + 0.5f) * s <= hi) i1++;
    return make_int2(i0, i1);
}

// align metric (noinline -> bit-identical scan vs argmax)
__device__ __noinline__ float align_fn(float x, float4 p, float ax, float ay, float4 g) {
    float pa = (p.z - p.x) * (p.w - p.y);
    float iw = fmaxf(fminf(p.z, g.z) - fmaxf(p.x, g.x), 0.f);
    float ih = fmaxf(fminf(p.w, g.w) - fmaxf(p.y, g.y), 0.f);
    float inter = iw * ih;
    float ga  = (g.z - g.x) * (g.w - g.y);
    float uni = pa + ga - inter + EPSF;
    float iou = inter / uni;
    float i2 = iou * iou;
    float i6 = i2 * i2 * i2;
    float ing = (ax >= g.x && ax <= g.z && ay >= g.y && ay <= g.w) ? 1.f : 0.f;
    float pdg = 1.f / (1.f + __expf(-x));
    return pdg * i6 * ing;
}

// ---------------- K1: fused streaming (decode family + BCE family) ------------------
__global__ __launch_bounds__(256, 5) void stream_kernel(
        const float* __restrict__ cls0, const float* __restrict__ cls1,
        const float* __restrict__ reg0, const float* __restrict__ reg1) {
    int bid = blockIdx.x, tid = threadIdx.x;
    int lane = tid & 31, wid = tid >> 5;

    if (bid < 2 * DECB) {
        // ----------------- decode family: thread per (anchor, side-group) ----------
        int br = bid / DECB;
        int t  = (bid % DECB) * 256 + tid;    // 0 .. BN*4-1
        int idx = t >> 2;                      // b*NN + n
        int g   = t & 3;
        const float* regs = br ? reg1 : reg0;
        const float4* r4 = (const float4*)(regs + (size_t)idx * 64 + g * RMv);
        float4 a0 = r4[0], a1 = r4[1], a2 = r4[2], a3 = r4[3];
        float v[16] = { a0.x,a0.y,a0.z,a0.w, a1.x,a1.y,a1.z,a1.w,
                        a2.x,a2.y,a2.z,a2.w, a3.x,a3.y,a3.z,a3.w };
        float mx = v[0];
#pragma unroll
        for (int j = 1; j < 16; j++) mx = fmaxf(mx, v[j]);
        float se = 0.f, sw = 0.f;
#pragma unroll
        for (int j = 0; j < 16; j++) {
            float e = __expf(v[j] - mx);
            se += e; sw += e * (float)j;
        }
        float dd = sw / se;
        int n = idx % NN;
        float ax, ay, s;
        anchor_of(n, ax, ay, s);
        float a = (g & 1) ? ay : ax;
        g_bbox[((size_t)br * BN + idx) * 4 + g] = (g < 2) ? (a - dd * s) : (a + dd * s);
    } else {
        // ----------------- BCE family (proven ~7 TB/s) ------------------------------
        int i0  = bid - 2 * DECB;              // 0..2099
        int brB = (i0 >= BCEHALF);
        const float4* c = (const float4*)(brB ? cls1 : cls0);
        size_t base = (size_t)(i0 - (brB ? BCEHALF : 0)) * F4PB + tid;
        float acc0 = 0.f, acc1 = 0.f;
#pragma unroll
        for (int half = 0; half < 2; half++) {
            float4 v[5];
#pragma unroll
            for (int j = 0; j < 5; j++)
                v[j] = c[base + (size_t)(half * 5 + j) * 256];
            float prod0 = 1.f, prod1 = 1.f;
#pragma unroll
            for (int j = 0; j < 5; j++) {
                float4 vv = v[j];
                acc0  += fmaxf(vv.x, 0.f) + fmaxf(vv.z, 0.f);
                acc1  += fmaxf(vv.y, 0.f) + fmaxf(vv.w, 0.f);
                prod0 *= (1.f + __expf(-fabsf(vv.x))) * (1.f + __expf(-fabsf(vv.z)));
                prod1 *= (1.f + __expf(-fabsf(vv.y))) * (1.f + __expf(-fabsf(vv.w)));
            }
            acc0 += __logf(prod0);
            acc1 += __logf(prod1);
        }
        __shared__ float shr[8];
        float v0 = warpSum(acc0 + acc1);
        if (lane == 0) shr[wid] = v0;
        __syncthreads();
        if (tid < 8) {
            float w0 = shr[tid];
#pragma unroll
            for (int o = 4; o > 0; o >>= 1) w0 += __shfl_down_sync(0xffu, w0, o);
            if (tid == 0) atomicAdd(&g_bce[brB], (double)w0);
        }
    }
}

// ---------------- K2: assigner, BOTH branches in parallel inside the block ----------
__global__ __launch_bounds__(ATH, 3) void assign_kernel(
        const float* __restrict__ cls0, const float* __restrict__ cls1,
        const float* __restrict__ reg0, const float* __restrict__ reg1,
        const int* __restrict__ gl, const float* __restrict__ gb,
        const float* __restrict__ mg, float* __restrict__ out) {
    int bm = blockIdx.x, tid = threadIdx.x;     // bm 0..511
    int lane = tid & 31, wid = tid >> 5;        // 10 warps
    int b = bm >> 5, m = bm & 31;

    __shared__ ull    skey[2][SLOTS];
    __shared__ float4 sgt[MM];
    __shared__ int    slab[MM];
    __shared__ int    sel[2][KMAX];
    __shared__ int    sbase[KMAX];              // zero-key baseline anchor ids
    __shared__ float  swacc[11][4];

    if (tid < MM) {
        sgt[tid]  = ((const float4*)gb)[b * MM + tid];
        slab[tid] = gl[b * MM + tid];
    }
    for (int i = tid; i < SLOTS; i += ATH) { skey[0][i] = 0ull; skey[1][i] = 0ull; }
    __syncthreads();
    float4 gt = sgt[m];
    int    lab = slab[m];
    float  mgv = mg[bm];

    // rectangle ranges per level (exact in-box index sets) — same for both branches
    int2 xr0 = axis_range(gt.x, gt.z, 8.f,  80);
    int2 yr0 = axis_range(gt.y, gt.w, 8.f,  80);
    int2 xr1 = axis_range(gt.x, gt.z, 16.f, 40);
    int2 yr1 = axis_range(gt.y, gt.w, 16.f, 40);
    int2 xr2 = axis_range(gt.x, gt.z, 32.f, 20);
    int2 yr2 = axis_range(gt.y, gt.w, 32.f, 20);
    int w0c = max(xr0.y - xr0.x + 1, 0), h0c = max(yr0.y - yr0.x + 1, 0);
    int w1c = max(xr1.y - xr1.x + 1, 0), h1c = max(yr1.y - yr1.x + 1, 0);
    int w2c = max(xr2.y - xr2.x + 1, 0), h2c = max(yr2.y - yr2.x + 1, 0);
    int cnt0 = w0c * h0c, cnt1 = w1c * h1c, cnt2 = w2c * h2c;
    int tot = cnt0 + cnt1 + cnt2;
    if (tot > SLOTS - KMAX) tot = SLOTS - KMAX;   // safety (never hit: max ~486)

    // zero-key baseline indices (same for both branches)
    if (tid == 0) {
        int got = 0;
        for (int n = 0; n < NN && got < KMAX; n++) {
            float ax, ay, sL;
            anchor_of(n, ax, ay, sL);
            bool in = (ax >= gt.x && ax <= gt.z && ay >= gt.y && ay <= gt.w);
            if (!in) { sbase[got] = n; got++; }
        }
    }
    __syncthreads();

    // ---- scan BOTH branches in one pass over 2*tot candidates ----------------------
    for (int t = tid; t < 2 * tot; t += ATH) {
        int br = (t >= tot);
        int u  = t - br * tot;
        int gx0, gy0, gw, gL, goff;
        float sL;
        if (u < cnt0)      { gx0 = xr0.x; gy0 = yr0.x; gw = w0c; gL = 80; goff = 0;    sL = 8.f; }
        else { u -= cnt0;
          if (u < cnt1)    { gx0 = xr1.x; gy0 = yr1.x; gw = w1c; gL = 40; goff = 6400; sL = 16.f; }
          else { u -= cnt1;  gx0 = xr2.x; gy0 = yr2.x; gw = w2c; gL = 20; goff = 8000; sL = 32.f; }
        }
        int iy = gy0 + u / gw;
        int ix = gx0 + u % gw;
        int n  = goff + iy * gL + ix;
        float ax = (ix + 0.5f) * sL, ay = (iy + 0.5f) * sL;
        const float4* bbox4 = (const float4*)g_bbox + (size_t)br * BN + (size_t)b * NN;
        const float* cls = br ? cls1 : cls0;
        float4 p = bbox4[n];
        float  x = cls[((size_t)b * NN + n) * NCLS + lab];
        float  a = align_fn(x, p, ax, ay, gt);
        skey[br][t - br * tot] = ((ull)__float_as_uint(a) << 32) |
                                 (ull)(0xFFFFFFFFu - (unsigned)n);
    }
    if (tid < KMAX) {
        ull bk = (ull)(0xFFFFFFFFu - (unsigned)sbase[tid]);
        skey[0][tot + tid] = bk;
        skey[1][tot + tid] = bk;
    }
    __syncthreads();

    // ---- concurrent selection: warp 0 -> br0 (K=10), warp 1 -> br1 (K=1) ----------
    if (wid < 2) {
        int brw = wid;
        int K = brw ? 1 : KMAX;
        for (int k = 0; k < K; k++) {
            ull best = 0; int bj = 0;
#pragma unroll
            for (int j = 0; j < SLOTS / 32; j++) {
                ull v = skey[brw][lane + j * 32];
                if (v > best) { best = v; bj = j; }
            }
            ull win = warpMaxU(best);
            if (best == win && win != 0ull) skey[brw][lane + bj * 32] = 0ull;
            if (lane == 0) sel[brw][k] = (int)(0xFFFFFFFFu - (unsigned)(win & 0xFFFFFFFFull));
        }
    }
    __syncthreads();

    // ---- winner tasks: 0..9 = br0 winners, 10 = br1 winner; warp w <- tasks w, w+10
    for (int task = wid; task < 11; task += 10) {
        int brt = (task == 10);
        int k   = brt ? 0 : task;
        float wbce = 0.f, wlbox = 0.f, wldfl = 0.f, wnp = 0.f;
        if (mgv > 0.f) {
            const float* cls  = brt ? cls1 : cls0;
            const float* regs = brt ? reg1 : reg0;
            const float4* bbox4 = (const float4*)g_bbox + (size_t)brt * BN + (size_t)b * NN;
            int n = sel[brt][k];
            float ax, ay, sL;
            anchor_of(n, ax, ay, sL);
            size_t idx = (size_t)b * NN + n;
            float4 p = bbox4[n];
            // lane-parallel argmax over the 32 GTs (first occurrence)
            float4 g = sgt[lane];
            float  x = cls[idx * NCLS + slab[lane]];
            bool in = (ax >= g.x && ax <= g.z && ay >= g.y && ay <= g.w);
            float a = in ? align_fn(x, p, ax, ay, g) : 0.f;
            ull key = ((ull)__float_as_uint(a) << 32) | (unsigned)(31 - lane);
            ull win = warpMaxU(key);
            int bmx = 31 - (int)(win & 0xFFFFFFFFull);
            if (bmx == m) {
                float xm = __shfl_sync(0xffffffffu, x, m);
                float t1x = gt.x, t1y = gt.y, t2x = gt.z, t2y = gt.w;
                float p1x = p.x, p1y = p.y, p2x = p.z, p2y = p.w;
                if (lane == 0) {
                    wnp = 1.f;
                    float iw = fmaxf(fminf(p2x, t2x) - fmaxf(p1x, t1x), 0.f);
                    float ih = fmaxf(fminf(p2y, t2y) - fmaxf(p1y, t1y), 0.f);
                    float inter = iw * ih;
                    float w1 = p2x - p1x, h1 = p2y - p1y;
                    float w2 = t2x - t1x, h2 = t2y - t1y;
                    float uni = w1 * h1 + w2 * h2 - inter + EPSF;
                    float iou = inter / uni;
                    wbce = -xm * iou;               // BCE target correction term
                    // CIoU (replicates reference bug: ch = max(p2y,t2y) - p1y)
                    float cwd = fmaxf(p2x, t2x) - fminf(p1x, t1x);
                    float chh = fmaxf(p2y, t2y) - p1y;
                    float c2 = cwd * cwd + chh * chh + EPSF;
                    float dx = p1x + p2x - t1x - t2x;
                    float dy = p1y + p2y - t1y - t2y;
                    float rho2 = (dx * dx + dy * dy) * 0.25f;
                    const float pi2 = 9.869604401089358f;
                    float dv = atanf(w2 / (h2 + EPSF)) - atanf(w1 / (h1 + EPSF));
                    float vv = (4.0f / pi2) * dv * dv;
                    float alpha = vv / (vv - iou + (1.0f + EPSF));
                    wlbox = 1.0f - (iou - (rho2 / c2 + vv * alpha));
                }
                // ---- lane-parallel DFL: lane holds r[lane], r[lane+32] --------------
                const float* r = regs + idx * 64;
                float v0 = r[lane];          // group = lane/16 (0 or 1)
                float v1 = r[lane + 32];     // group = 2 + lane/16
                float m0 = v0, m1 = v1;
#pragma unroll
                for (int o = 8; o > 0; o >>= 1) {
                    m0 = fmaxf(m0, __shfl_xor_sync(0xffffffffu, m0, o));
                    m1 = fmaxf(m1, __shfl_xor_sync(0xffffffffu, m1, o));
                }
                float e0 = __expf(v0 - m0), e1 = __expf(v1 - m1);
#pragma unroll
                for (int o = 8; o > 0; o >>= 1) {
                    e0 += __shfl_xor_sync(0xffffffffu, e0, o);
                    e1 += __shfl_xor_sync(0xffffffffu, e1, o);
                }
                float lse0 = __logf(e0) + m0;   // group (lane<16?0:1)
                float lse1 = __logf(e1) + m1;   // group (lane<16?2:3)
                int gsel = lane & 3;
                float tg = (gsel == 0) ? (ax - t1x) / sL :
                           (gsel == 1) ? (ay - t1y) / sL :
                           (gsel == 2) ? (t2x - ax) / sL : (t2y - ay) / sL;
                float vc = fminf(fmaxf(tg, 0.f), 14.99f);
                int   tl = (int)vc;
                float wwl = (float)(tl + 1) - vc;
                float wwr = 1.0f - wwl;
                int half = (gsel & 1) * 16;
                float lA  = __shfl_sync(0xffffffffu, lse0, half);
                float lB  = __shfl_sync(0xffffffffu, lse1, half);
                float rA0 = __shfl_sync(0xffffffffu, v0, half + tl);
                float rB0 = __shfl_sync(0xffffffffu, v1, half + tl);
                float rA1 = __shfl_sync(0xffffffffu, v0, half + tl + 1);
                float rB1 = __shfl_sync(0xffffffffu, v1, half + tl + 1);
                float lseg = (gsel < 2) ? lA : lB;
                float rtl  = (gsel < 2) ? rA0 : rB0;
                float rtr  = (gsel < 2) ? rA1 : rB1;
                float dfl = -(rtl - lseg) * wwl - (rtr - lseg) * wwr;
                wldfl = (lane < 4) ? dfl : 0.f;
            }
        }
        float vals[4] = { wbce, wlbox, wldfl, wnp };
#pragma unroll
        for (int q = 0; q < 4; q++) {
            float v = warpSum(vals[q]);
            if (lane == 0) swacc[task][q] = v;
        }
    }
    __syncthreads();

    // ---- combine: warp 0 -> br0 tasks 0..9; warp 1 -> br1 task 10 -------------------
    if (wid == 0) {
#pragma unroll
        for (int q = 0; q < 4; q++) {
            float v = (lane < KMAX) ? swacc[lane][q] : 0.f;
            v = warpSum(v);
            if (lane == 0 && v != 0.f) atomicAdd(&g_acc[0 * 4 + q], (double)v);
        }
    } else if (wid == 1) {
        if (lane == 0) {
#pragma unroll
            for (int q = 0; q < 4; q++) {
                float v = swacc[10][q];
                if (v != 0.f) atomicAdd(&g_acc[1 * 4 + q], (double)v);
            }
        }
    }
    __syncthreads();

    // ---- ticketed O(1) final ---------------------------------------------------------
    if (tid == 0) {
        __threadfence();
        if (atomicAdd(&g_ticket, 1u) == ABLK - 1) {
            __threadfence();
            double t[2], c[2], bx[2], df[2];
            for (int br2 = 0; br2 < 2; br2++) {
                double bceT  = g_bce[br2] + g_acc[br2 * 4 + 0];
                double lboxT = g_acc[br2 * 4 + 1];
                double ldflT = g_acc[br2 * 4 + 2];
                double nfg   = fmax(g_acc[br2 * 4 + 3], 1.0);
                c[br2]  = bceT / nfg;
                bx[br2] = lboxT / nfg;
                df[br2] = ldflT / (nfg * 4.0);
                t[br2]  = c[br2] + bx[br2] * 7.5 + df[br2] * 1.5;
            }
            out[0] = (float)(t[0] + t[1]);
            out[1] = (float)(c[0] + c[1]);
            out[2] = (float)(bx[0] + bx[1]);
            out[3] = (float)(df[0] + df[1]);
            out[4] = (float)t[0];
            out[5] = (float)t[1];
            // reset persistent state for the next graph replay
            g_bce[0] = 0.0; g_bce[1] = 0.0;
#pragma unroll
            for (int q = 0; q < 8; q++) g_acc[q] = 0.0;
            __threadfence();
            g_ticket = 0;
        }
    }
}

// ---------------- launch ---------------------------------------------------------------
extern "C" void kernel_launch(void* const* d_in, const int* in_sizes, int n_in,
                              void* d_out, int out_size) {
    const float* cls0 = (const float*)d_in[0];
    const float* reg0 = (const float*)d_in[1];
    const float* cls1 = (const float*)d_in[2];
    const float* reg1 = (const float*)d_in[3];
    const int*   gl   = (const int*)d_in[6];
    const float* gb   = (const float*)d_in[7];
    const float* mg   = (const float*)d_in[8];
    float* out = (float*)d_out;

    stream_kernel<<<2 * DECB + BCEB, 256>>>(cls0, cls1, reg0, reg1);
    assign_kernel<<<ABLK, ATH>>>(cls0, cls1, reg0, reg1, gl, gb, mg, out);
}

// round 17
// speedup vs baseline: 1.4968x; 1.1249x over previous
#include <cuda_runtime.h>
#include <math.h>

#define BB    16
#define NN    8400
#define NCLS  80
#define MM    32
#define RMv   16
#define KMAX  10
#define EPSF  1e-7f
#define BN    (BB * NN)
#define ABLK  512              // assigner blocks: one per (b,m), both branches parallel
#define DECB  2100             // decode blocks per branch: 2100*256 = BN*4 exactly
#define BCEB  2100
#define BCEHALF 1050
#define F4PB  2560
#define NV4B  2688000          // BN*NCLS/4 per branch
#define SLOTS 512
#define ATH   256              // assigner threads (8 warps) -> 5 blocks/SM, 1 wave

typedef unsigned long long ull;

// ---------------- scratch / accumulators -------------------------------------------
__device__ float    g_bbox[2 * (size_t)BN * 4];    // decoded boxes per (br, idx)
__device__ double   g_bce[2] = {0.0, 0.0};
__device__ double   g_acc[8] = {0,0,0,0,0,0,0,0};  // [br*4 + {bce_t, lbox, ldfl, npos}]
__device__ unsigned g_ticket = 0;

// ---------------- helpers -----------------------------------------------------------
__device__ __forceinline__ float warpSum(float v) {
#pragma unroll
    for (int o = 16; o > 0; o >>= 1) v += __shfl_down_sync(0xffffffffu, v, o);
    return v;
}
__device__ __forceinline__ ull warpMaxU(ull v) {
#pragma unroll
    for (int o = 16; o > 0; o >>= 1) {
        ull other = __shfl_xor_sync(0xffffffffu, v, o);
        if (other > v) v = other;
    }
    return v;
}

__device__ __constant__ int LS[3]   = {8, 16, 32};
__device__ __constant__ int LG[3]   = {80, 40, 20};
__device__ __constant__ int LOFF[3] = {0, 6400, 8000};

__device__ __forceinline__ void anchor_of(int n, float& ax, float& ay, float& s) {
    int l = (n < 6400) ? 0 : ((n < 8000) ? 1 : 2);
    int g = LG[l], loc = n - LOFF[l];
    int iy = loc / g, ix = loc % g;
    s = (float)LS[l];
    ax = (ix + 0.5f) * s;
    ay = (iy + 0.5f) * s;
}

// index range [i0,i1] with (i+0.5)*s inside [lo,hi]; exact wrt float predicate
__device__ __forceinline__ int2 axis_range(float lo, float hi, float s, int g) {
    int i0 = (int)floorf(lo / s - 0.5f);
    if (i0 < 0) i0 = 0;
    while (i0 < g && (i0 + 0.5f) * s < lo) i0++;
    while (i0 > 0 && ((i0 - 1) + 0.5f) * s >= lo) i0--;
    int i1 = (int)ceilf(hi / s - 0.5f);
    if (i1 > g - 1) i1 = g - 1;
    while (i1 >= 0 && (i1 + 0.5f) * s > hi) i1--;
    while (i1 < g - 1 && ((i1 + 1) + 0.5f) * s <= hi) i1++;
    return make_int2(i0, i1);
}

// align metric (noinline -> bit-identical scan vs argmax)
__device__ __noinline__ float align_fn(float x, float4 p, float ax, float ay, float4 g) {
    float pa = (p.z - p.x) * (p.w - p.y);
    float iw = fmaxf(fminf(p.z, g.z) - fmaxf(p.x, g.x), 0.f);
    float ih = fmaxf(fminf(p.w, g.w) - fmaxf(p.y, g.y), 0.f);
    float inter = iw * ih;
    float ga  = (g.z - g.x) * (g.w - g.y);
    float uni = pa + ga - inter + EPSF;
    float iou = inter / uni;
    float i2 = iou * iou;
    float i6 = i2 * i2 * i2;
    float ing = (ax >= g.x && ax <= g.z && ay >= g.y && ay <= g.w) ? 1.f : 0.f;
    float pdg = 1.f / (1.f + __expf(-x));
    return pdg * i6 * ing;
}

// ---------------- K1: fused streaming (decode family + BCE family) ------------------
__global__ __launch_bounds__(256, 5) void stream_kernel(
        const float* __restrict__ cls0, const float* __restrict__ cls1,
        const float* __restrict__ reg0, const float* __restrict__ reg1) {
    int bid = blockIdx.x, tid = threadIdx.x;
    int lane = tid & 31, wid = tid >> 5;

    if (bid < 2 * DECB) {
        // ----------------- decode family: thread per (anchor, side-group) ----------
        int br = bid / DECB;
        int t  = (bid % DECB) * 256 + tid;    // 0 .. BN*4-1
        int idx = t >> 2;                      // b*NN + n
        int g   = t & 3;
        const float* regs = br ? reg1 : reg0;
        const float4* r4 = (const float4*)(regs + (size_t)idx * 64 + g * RMv);
        float4 a0 = r4[0], a1 = r4[1], a2 = r4[2], a3 = r4[3];
        float v[16] = { a0.x,a0.y,a0.z,a0.w, a1.x,a1.y,a1.z,a1.w,
                        a2.x,a2.y,a2.z,a2.w, a3.x,a3.y,a3.z,a3.w };
        float mx = v[0];
#pragma unroll
        for (int j = 1; j < 16; j++) mx = fmaxf(mx, v[j]);
        float se = 0.f, sw = 0.f;
#pragma unroll
        for (int j = 0; j < 16; j++) {
            float e = __expf(v[j] - mx);
            se += e; sw += e * (float)j;
        }
        float dd = sw / se;
        int n = idx % NN;
        float ax, ay, s;
        anchor_of(n, ax, ay, s);
        float a = (g & 1) ? ay : ax;
        g_bbox[((size_t)br * BN + idx) * 4 + g] = (g < 2) ? (a - dd * s) : (a + dd * s);
    } else {
        // ----------------- BCE family (proven ~7 TB/s) ------------------------------
        int i0  = bid - 2 * DECB;              // 0..2099
        int brB = (i0 >= BCEHALF);
        const float4* c = (const float4*)(brB ? cls1 : cls0);
        size_t base = (size_t)(i0 - (brB ? BCEHALF : 0)) * F4PB + tid;
        float acc0 = 0.f, acc1 = 0.f;
#pragma unroll
        for (int half = 0; half < 2; half++) {
            float4 v[5];
#pragma unroll
            for (int j = 0; j < 5; j++)
                v[j] = c[base + (size_t)(half * 5 + j) * 256];
            float prod0 = 1.f, prod1 = 1.f;
#pragma unroll
            for (int j = 0; j < 5; j++) {
                float4 vv = v[j];
                acc0  += fmaxf(vv.x, 0.f) + fmaxf(vv.z, 0.f);
                acc1  += fmaxf(vv.y, 0.f) + fmaxf(vv.w, 0.f);
                prod0 *= (1.f + __expf(-fabsf(vv.x))) * (1.f + __expf(-fabsf(vv.z)));
                prod1 *= (1.f + __expf(-fabsf(vv.y))) * (1.f + __expf(-fabsf(vv.w)));
            }
            acc0 += __logf(prod0);
            acc1 += __logf(prod1);
        }
        __shared__ float shr[8];
        float v0 = warpSum(acc0 + acc1);
        if (lane == 0) shr[wid] = v0;
        __syncthreads();
        if (tid < 8) {
            float w0 = shr[tid];
#pragma unroll
            for (int o = 4; o > 0; o >>= 1) w0 += __shfl_down_sync(0xffu, w0, o);
            if (tid == 0) atomicAdd(&g_bce[brB], (double)w0);
        }
    }
}

// ---------------- K2: assigner, 8 warps, single wave ---------------------------------
__global__ __launch_bounds__(ATH, 5) void assign_kernel(
        const float* __restrict__ cls0, const float* __restrict__ cls1,
        const float* __restrict__ reg0, const float* __restrict__ reg1,
        const int* __restrict__ gl, const float* __restrict__ gb,
        const float* __restrict__ mg, float* __restrict__ out) {
    int bm = blockIdx.x, tid = threadIdx.x;     // bm 0..511
    int lane = tid & 31, wid = tid >> 5;        // 8 warps
    int b = bm >> 5, m = bm & 31;

    __shared__ ull    skey[2][SLOTS];
    __shared__ float4 sgt[MM];
    __shared__ int    slab[MM];
    __shared__ int    sel[2][KMAX];
    __shared__ int    sbase[KMAX];              // zero-key baseline anchor ids
    __shared__ float  swacc[11][4];

    if (tid < MM) {
        sgt[tid]  = ((const float4*)gb)[b * MM + tid];
        slab[tid] = gl[b * MM + tid];
    }
    for (int i = tid; i < SLOTS; i += ATH) { skey[0][i] = 0ull; skey[1][i] = 0ull; }
    __syncthreads();
    float4 gt = sgt[m];
    int    lab = slab[m];
    float  mgv = mg[bm];

    // rectangle ranges per level (exact in-box index sets) — same for both branches
    int2 xr0 = axis_range(gt.x, gt.z, 8.f,  80);
    int2 yr0 = axis_range(gt.y, gt.w, 8.f,  80);
    int2 xr1 = axis_range(gt.x, gt.z, 16.f, 40);
    int2 yr1 = axis_range(gt.y, gt.w, 16.f, 40);
    int2 xr2 = axis_range(gt.x, gt.z, 32.f, 20);
    int2 yr2 = axis_range(gt.y, gt.w, 32.f, 20);
    int w0c = max(xr0.y - xr0.x + 1, 0), h0c = max(yr0.y - yr0.x + 1, 0);
    int w1c = max(xr1.y - xr1.x + 1, 0), h1c = max(yr1.y - yr1.x + 1, 0);
    int w2c = max(xr2.y - xr2.x + 1, 0), h2c = max(yr2.y - yr2.x + 1, 0);
    int cnt0 = w0c * h0c, cnt1 = w1c * h1c, cnt2 = w2c * h2c;
    int tot = cnt0 + cnt1 + cnt2;
    if (tot > SLOTS - KMAX) tot = SLOTS - KMAX;   // safety (never hit: max ~486)

    // zero-key baseline indices (same for both branches)
    if (tid == 0) {
        int got = 0;
        for (int n = 0; n < NN && got < KMAX; n++) {
            float ax, ay, sL;
            anchor_of(n, ax, ay, sL);
            bool in = (ax >= gt.x && ax <= gt.z && ay >= gt.y && ay <= gt.w);
            if (!in) { sbase[got] = n; got++; }
        }
    }
    __syncthreads();

    // ---- scan BOTH branches in one pass over 2*tot candidates ----------------------
    for (int t = tid; t < 2 * tot; t += ATH) {
        int br = (t >= tot);
        int u  = t - br * tot;
        int gx0, gy0, gw, gL, goff;
        float sL;
        if (u < cnt0)      { gx0 = xr0.x; gy0 = yr0.x; gw = w0c; gL = 80; goff = 0;    sL = 8.f; }
        else { u -= cnt0;
          if (u < cnt1)    { gx0 = xr1.x; gy0 = yr1.x; gw = w1c; gL = 40; goff = 6400; sL = 16.f; }
          else { u -= cnt1;  gx0 = xr2.x; gy0 = yr2.x; gw = w2c; gL = 20; goff = 8000; sL = 32.f; }
        }
        int iy = gy0 + u / gw;
        int ix = gx0 + u % gw;
        int n  = goff + iy * gL + ix;
        float ax = (ix + 0.5f) * sL, ay = (iy + 0.5f) * sL;
        const float4* bbox4 = (const float4*)g_bbox + (size_t)br * BN + (size_t)b * NN;
        const float* cls = br ? cls1 : cls0;
        float4 p = bbox4[n];
        float  x = cls[((size_t)b * NN + n) * NCLS + lab];
        float  a = align_fn(x, p, ax, ay, gt);
        skey[br][t - br * tot] = ((ull)__float_as_uint(a) << 32) |
                                 (ull)(0xFFFFFFFFu - (unsigned)n);
    }
    if (tid < KMAX) {
        ull bk = (ull)(0xFFFFFFFFu - (unsigned)sbase[tid]);
        skey[0][tot + tid] = bk;
        skey[1][tot + tid] = bk;
    }
    __syncthreads();

    // ---- concurrent selection: warp 0 -> br0 (K=10), warp 1 -> br1 (K=1) ----------
    if (wid < 2) {
        int brw = wid;
        int K = brw ? 1 : KMAX;
        for (int k = 0; k < K; k++) {
            ull best = 0; int bj = 0;
#pragma unroll
            for (int j = 0; j < SLOTS / 32; j++) {
                ull v = skey[brw][lane + j * 32];
                if (v > best) { best = v; bj = j; }
            }
            ull win = warpMaxU(best);
            if (best == win && win != 0ull) skey[brw][lane + bj * 32] = 0ull;
            if (lane == 0) sel[brw][k] = (int)(0xFFFFFFFFu - (unsigned)(win & 0xFFFFFFFFull));
        }
    }
    __syncthreads();

    // ---- winner tasks: 0..9 = br0 winners, 10 = br1 winner; warp w <- w, w+8 -------
    for (int task = wid; task < 11; task += 8) {
        int brt = (task == 10);
        int k   = brt ? 0 : task;
        float wbce = 0.f, wlbox = 0.f, wldfl = 0.f, wnp = 0.f;
        if (mgv > 0.f) {
            const float* cls  = brt ? cls1 : cls0;
            const float* regs = brt ? reg1 : reg0;
            const float4* bbox4 = (const float4*)g_bbox + (size_t)brt * BN + (size_t)b * NN;
            int n = sel[brt][k];
            float ax, ay, sL;
            anchor_of(n, ax, ay, sL);
            size_t idx = (size_t)b * NN + n;
            float4 p = bbox4[n];
            // lane-parallel argmax over the 32 GTs (first occurrence)
            float4 g = sgt[lane];
            float  x = cls[idx * NCLS + slab[lane]];
            bool in = (ax >= g.x && ax <= g.z && ay >= g.y && ay <= g.w);
            float a = in ? align_fn(x, p, ax, ay, g) : 0.f;
            ull key = ((ull)__float_as_uint(a) << 32) | (unsigned)(31 - lane);
            ull win = warpMaxU(key);
            int bmx = 31 - (int)(win & 0xFFFFFFFFull);
            if (bmx == m) {
                float xm = __shfl_sync(0xffffffffu, x, m);
                float t1x = gt.x, t1y = gt.y, t2x = gt.z, t2y = gt.w;
                float p1x = p.x, p1y = p.y, p2x = p.z, p2y = p.w;
                if (lane == 0) {
                    wnp = 1.f;
                    float iw = fmaxf(fminf(p2x, t2x) - fmaxf(p1x, t1x), 0.f);
                    float ih = fmaxf(fminf(p2y, t2y) - fmaxf(p1y, t1y), 0.f);
                    float inter = iw * ih;
                    float w1 = p2x - p1x, h1 = p2y - p1y;
                    float w2 = t2x - t1x, h2 = t2y - t1y;
                    float uni = w1 * h1 + w2 * h2 - inter + EPSF;
                    float iou = inter / uni;
                    wbce = -xm * iou;               // BCE target correction term
                    // CIoU (replicates reference bug: ch = max(p2y,t2y) - p1y)
                    float cwd = fmaxf(p2x, t2x) - fminf(p1x, t1x);
                    float chh = fmaxf(p2y, t2y) - p1y;
                    float c2 = cwd * cwd + chh * chh + EPSF;
                    float dx = p1x + p2x - t1x - t2x;
                    float dy = p1y + p2y - t1y - t2y;
                    float rho2 = (dx * dx + dy * dy) * 0.25f;
                    const float pi2 = 9.869604401089358f;
                    float dv = atanf(w2 / (h2 + EPSF)) - atanf(w1 / (h1 + EPSF));
                    float vv = (4.0f / pi2) * dv * dv;
                    float alpha = vv / (vv - iou + (1.0f + EPSF));
                    wlbox = 1.0f - (iou - (rho2 / c2 + vv * alpha));
                }
                // ---- lane-parallel DFL: lane holds r[lane], r[lane+32] --------------
                const float* r = regs + idx * 64;
                float v0 = r[lane];          // group = lane/16 (0 or 1)
                float v1 = r[lane + 32];     // group = 2 + lane/16
                float m0 = v0, m1 = v1;
#pragma unroll
                for (int o = 8; o > 0; o >>= 1) {
                    m0 = fmaxf(m0, __shfl_xor_sync(0xffffffffu, m0, o));
                    m1 = fmaxf(m1, __shfl_xor_sync(0xffffffffu, m1, o));
                }
                float e0 = __expf(v0 - m0), e1 = __expf(v1 - m1);
#pragma unroll
                for (int o = 8; o > 0; o >>= 1) {
                    e0 += __shfl_xor_sync(0xffffffffu, e0, o);
                    e1 += __shfl_xor_sync(0xffffffffu, e1, o);
                }
                float lse0 = __logf(e0) + m0;   // group (lane<16?0:1)
                float lse1 = __logf(e1) + m1;   // group (lane<16?2:3)
                int gsel = lane & 3;
                float tg = (gsel == 0) ? (ax - t1x) / sL :
                           (gsel == 1) ? (ay - t1y) / sL :
                           (gsel == 2) ? (t2x - ax) / sL : (t2y - ay) / sL;
                float vc = fminf(fmaxf(tg, 0.f), 14.99f);
                int   tl = (int)vc;
                float wwl = (float)(tl + 1) - vc;
                float wwr = 1.0f - wwl;
                int half = (gsel & 1) * 16;
                float lA  = __shfl_sync(0xffffffffu, lse0, half);
                float lB  = __shfl_sync(0xffffffffu, lse1, half);
                float rA0 = __shfl_sync(0xffffffffu, v0, half + tl);
                float rB0 = __shfl_sync(0xffffffffu, v1, half + tl);
                float rA1 = __shfl_sync(0xffffffffu, v0, half + tl + 1);
                float rB1 = __shfl_sync(0xffffffffu, v1, half + tl + 1);
                float lseg = (gsel < 2) ? lA : lB;
                float rtl  = (gsel < 2) ? rA0 : rB0;
                float rtr  = (gsel < 2) ? rA1 : rB1;
                float dfl = -(rtl - lseg) * wwl - (rtr - lseg) * wwr;
                wldfl = (lane < 4) ? dfl : 0.f;
            }
        }
        float vals[4] = { wbce, wlbox, wldfl, wnp };
#pragma unroll
        for (int q = 0; q < 4; q++) {
            float v = warpSum(vals[q]);
            if (lane == 0) swacc[task][q] = v;
        }
    }
    __syncthreads();

    // ---- combine: warp 0 -> br0 tasks 0..9; warp 1 -> br1 task 10 -------------------
    if (wid == 0) {
#pragma unroll
        for (int q = 0; q < 4; q++) {
            float v = (lane < KMAX) ? swacc[lane][q] : 0.f;
            v = warpSum(v);
            if (lane == 0 && v != 0.f) atomicAdd(&g_acc[0 * 4 + q], (double)v);
        }
    } else if (wid == 1) {
        if (lane == 0) {
#pragma unroll
            for (int q = 0; q < 4; q++) {
                float v = swacc[10][q];
                if (v != 0.f) atomicAdd(&g_acc[1 * 4 + q], (double)v);
            }
        }
    }
    __syncthreads();

    // ---- ticketed O(1) final ---------------------------------------------------------
    if (tid == 0) {
        __threadfence();
        if (atomicAdd(&g_ticket, 1u) == ABLK - 1) {
            __threadfence();
            double t[2], c[2], bx[2], df[2];
            for (int br2 = 0; br2 < 2; br2++) {
                double bceT  = g_bce[br2] + g_acc[br2 * 4 + 0];
                double lboxT = g_acc[br2 * 4 + 1];
                double ldflT = g_acc[br2 * 4 + 2];
                double nfg   = fmax(g_acc[br2 * 4 + 3], 1.0);
                c[br2]  = bceT / nfg;
                bx[br2] = lboxT / nfg;
                df[br2] = ldflT / (nfg * 4.0);
                t[br2]  = c[br2] + bx[br2] * 7.5 + df[br2] * 1.5;
            }
            out[0] = (float)(t[0] + t[1]);
            out[1] = (float)(c[0] + c[1]);
            out[2] = (float)(bx[0] + bx[1]);
            out[3] = (float)(df[0] + df[1]);
            out[4] = (float)t[0];
            out[5] = (float)t[1];
            // reset persistent state for the next graph replay
            g_bce[0] = 0.0; g_bce[1] = 0.0;
#pragma unroll
            for (int q = 0; q < 8; q++) g_acc[q] = 0.0;
            __threadfence();
            g_ticket = 0;
        }
    }
}

// ---------------- launch ---------------------------------------------------------------
extern "C" void kernel_launch(void* const* d_in, const int* in_sizes, int n_in,
                              void* d_out, int out_size) {
    const float* cls0 = (const float*)d_in[0];
    const float* reg0 = (const float*)d_in[1];
    const float* cls1 = (const float*)d_in[2];
    const float* reg1 = (const float*)d_in[3];
    const int*   gl   = (const int*)d_in[6];
    const float* gb   = (const float*)d_in[7];
    const float* mg   = (const float*)d_in[8];
    float* out = (float*)d_out;

    stream_kernel<<<2 * DECB + BCEB, 256>>>(cls0, cls1, reg0, reg1);
    assign_kernel<<<ABLK, ATH>>>(cls0, cls1, reg0, reg1, gl, gb, mg, out);
}